// round 1
// baseline (speedup 1.0000x reference)
#include <cuda_runtime.h>
#include <math.h>

// Problem constants
#define CDIM 512
#define CB   64
#define CL   128
#define CDI  1024     // D_INNER
#define CDS  16       // D_STATE
#define CM   (CB*CL)  // 8192 rows

// ---------------------------------------------------------------------------
// Scratch (device bss — no allocation at runtime)
// ---------------------------------------------------------------------------
__device__ __align__(16) float g_fts_pad[CB*130*CDIM];  // padded conv input (B,130,512)
__device__ __align__(16) float g_wt[CDIM*3*CDIM];       // conv weights (co, k, ci)
__device__ __align__(16) float g_conv[CM*CDIM];         // conv output
__device__ __align__(16) float g_fts0[CM*CDIM];         // post LN+relu (residual + mamba input)
__device__ __align__(16) float g_xz[CM*2*CDI];          // in_proj out
__device__ __align__(16) float g_xc[CM*CDI];            // silu(depthwise conv)
__device__ __align__(16) float g_dbc[CM*64];            // x_proj out (dt_r 32 | B 16 | C 16)
__device__ __align__(16) float g_dt[CM*CDI];            // softplus dt
__device__ __align__(16) float g_ys[CM*CDI];            // scan out * silu(z)
__device__ __align__(16) float g_m[CM*CDIM];            // out_proj out
__device__ __align__(16) float g_A[CDI*CDS];            // -exp(A_log)
__device__ __align__(16) float g_coff[CM];

// ---------------------------------------------------------------------------
// Math helpers
// ---------------------------------------------------------------------------
__device__ __forceinline__ float softplusf(float x) {
    if (x > 20.f) return x;
    return log1pf(__expf(x));
}
__device__ __forceinline__ float siluf(float x) {
    return x / (1.f + __expf(-x));
}
// FFMA-only fast exp (avoids MUFU bottleneck in the scan).
// exp(x) = 2^(x*log2e); round-to-nearest via magic constant, deg-5 Taylor on
// the fraction (|err| ~2e-6 rel), exponent spliced via int add on the bits.
__device__ __forceinline__ float fexp(float x) {
    x = fmaxf(-80.f, fminf(80.f, x));
    float t = x * 1.4426950408889634f;
    float r = t + 12582912.0f;              // 1.5*2^23 : round-to-nearest-int
    int   n = __float_as_int(r) - 0x4B400000;
    float f = t - (r - 12582912.0f);        // in [-0.5, 0.5]
    float y = f * 0.6931471805599453f;      // f*ln2
    float p = fmaf(y, 8.3333333e-3f, 4.1666667e-2f);
    p = fmaf(y, p, 1.6666667e-1f);
    p = fmaf(y, p, 5.0e-1f);
    p = fmaf(y, p, 1.0f);
    p = fmaf(y, p, 1.0f);
    return __int_as_float(__float_as_int(p) + (n << 23));
}

// Block reductions for 128-thread blocks (4 warps)
__device__ __forceinline__ void blockRed2(float& a, float& b) {
    #pragma unroll
    for (int o = 16; o; o >>= 1) {
        a += __shfl_xor_sync(0xffffffffu, a, o);
        b += __shfl_xor_sync(0xffffffffu, b, o);
    }
    __shared__ float sa[4], sb[4];
    int w = threadIdx.x >> 5;
    if ((threadIdx.x & 31) == 0) { sa[w] = a; sb[w] = b; }
    __syncthreads();
    a = sa[0] + sa[1] + sa[2] + sa[3];
    b = sb[0] + sb[1] + sb[2] + sb[3];
    __syncthreads();
}
__device__ __forceinline__ float blockRed1(float a) {
    #pragma unroll
    for (int o = 16; o; o >>= 1) a += __shfl_xor_sync(0xffffffffu, a, o);
    __shared__ float sc[4];
    int w = threadIdx.x >> 5;
    if ((threadIdx.x & 31) == 0) sc[w] = a;
    __syncthreads();
    float t = sc[0] + sc[1] + sc[2] + sc[3];
    __syncthreads();
    return t;
}

// ---------------------------------------------------------------------------
// Prep kernels
// ---------------------------------------------------------------------------
__global__ void pad_k(const float* __restrict__ spt, const float* __restrict__ qry) {
    int idx = blockIdx.x * blockDim.x + threadIdx.x;
    if (idx >= CB * 130 * CDIM) return;
    int b = idx / (130 * CDIM);
    int r = idx % (130 * CDIM);
    int l = r / CDIM;
    int c = r % CDIM;
    float v = 0.f;
    if (l >= 1 && l <= 128) {
        int ll = l - 1;
        v = (ll < 64) ? spt[b * 32768 + ll * CDIM + c]
                      : qry[b * 32768 + (ll - 64) * CDIM + c];
    }
    g_fts_pad[idx] = v;
}
__global__ void wt_k(const float* __restrict__ cw) {
    int idx = blockIdx.x * blockDim.x + threadIdx.x;
    if (idx >= CDIM * 1536) return;
    int co = idx / 1536;
    int r  = idx % 1536;
    int k  = r / CDIM;
    int ci = r % CDIM;
    g_wt[idx] = cw[(co * CDIM + ci) * 3 + k];
}
__global__ void a_k(const float* __restrict__ alog) {
    int idx = blockIdx.x * blockDim.x + threadIdx.x;
    if (idx >= CDI * CDS) return;
    g_A[idx] = -expf(alog[idx]);
}

// ---------------------------------------------------------------------------
// Generic fp32 NT GEMM: C[m][n] = sum_k A_row(m)[k] * W[n*ldw+k]  (+epilogue)
// A_row(m) = A + (m/rb)*rbs + (m%rb)*rs   (handles conv window addressing)
// EPI: 0 = none, 1 = +bias, 2 = softplus(+bias)
// ---------------------------------------------------------------------------
template<int BM, int BN, int BK, int TM, int TN, int EPI>
__global__ __launch_bounds__((BM/TM)*(BN/TN))
void sgemm_nt(const float* __restrict__ A, const float* __restrict__ W,
              const float* __restrict__ bias, float* __restrict__ C,
              int K, int rb, long rbs, long rs, int ldw, int ldc)
{
    constexpr int TX = BN / TN, TY = BM / TM, NT = TX * TY;
    constexpr int K4 = BK / 4;
    constexpr int ROWS_PER = NT / K4;
    static_assert(NT == 256, "thread count");

    __shared__ __align__(16) float As[BK][BM];
    __shared__ __align__(16) float Ws[BK][BN];

    int tid = threadIdx.x;
    int m0 = blockIdx.y * BM, n0 = blockIdx.x * BN;
    int tx = tid % TX, ty = tid / TX;
    int arow = tid / K4, ac4 = (tid % K4) * 4;

    float acc[TM][TN];
    #pragma unroll
    for (int i = 0; i < TM; i++)
        #pragma unroll
        for (int j = 0; j < TN; j++) acc[i][j] = 0.f;

    for (int k0 = 0; k0 < K; k0 += BK) {
        #pragma unroll
        for (int r = arow; r < BM; r += ROWS_PER) {
            int grow = m0 + r;
            const float* ap = A + (long)(grow / rb) * rbs + (long)(grow % rb) * rs + k0 + ac4;
            float4 v = *(const float4*)ap;
            As[ac4 + 0][r] = v.x; As[ac4 + 1][r] = v.y;
            As[ac4 + 2][r] = v.z; As[ac4 + 3][r] = v.w;
        }
        #pragma unroll
        for (int r = arow; r < BN; r += ROWS_PER) {
            const float* wp = W + (long)(n0 + r) * ldw + k0 + ac4;
            float4 v = *(const float4*)wp;
            Ws[ac4 + 0][r] = v.x; Ws[ac4 + 1][r] = v.y;
            Ws[ac4 + 2][r] = v.z; Ws[ac4 + 3][r] = v.w;
        }
        __syncthreads();
        #pragma unroll
        for (int k = 0; k < BK; k++) {
            float a[TM], wv[TN];
            #pragma unroll
            for (int i = 0; i < TM; i += 4) {
                float4 t = *(const float4*)&As[k][ty * TM + i];
                a[i] = t.x; a[i+1] = t.y; a[i+2] = t.z; a[i+3] = t.w;
            }
            #pragma unroll
            for (int j = 0; j < TN; j += 4) {
                float4 t = *(const float4*)&Ws[k][tx * TN + j];
                wv[j] = t.x; wv[j+1] = t.y; wv[j+2] = t.z; wv[j+3] = t.w;
            }
            #pragma unroll
            for (int i = 0; i < TM; i++)
                #pragma unroll
                for (int j = 0; j < TN; j++)
                    acc[i][j] = fmaf(a[i], wv[j], acc[i][j]);
        }
        __syncthreads();
    }

    #pragma unroll
    for (int i = 0; i < TM; i++) {
        int gm = m0 + ty * TM + i;
        float* cp = C + (long)gm * ldc + n0 + tx * TN;
        #pragma unroll
        for (int j = 0; j < TN; j += 4) {
            float4 v;
            float e0 = acc[i][j], e1 = acc[i][j+1], e2 = acc[i][j+2], e3 = acc[i][j+3];
            if (EPI >= 1) {
                int gn = n0 + tx * TN + j;
                e0 += bias[gn]; e1 += bias[gn+1]; e2 += bias[gn+2]; e3 += bias[gn+3];
            }
            if (EPI == 2) {
                e0 = softplusf(e0); e1 = softplusf(e1);
                e2 = softplusf(e2); e3 = softplusf(e3);
            }
            v.x = e0; v.y = e1; v.z = e2; v.w = e3;
            *(float4*)(cp + j) = v;
        }
    }
}

// ---------------------------------------------------------------------------
// LayerNorm(512) + ReLU per row
// ---------------------------------------------------------------------------
__global__ void ln_relu_k(const float* __restrict__ in, const float* __restrict__ w,
                          const float* __restrict__ b, float* __restrict__ out)
{
    int row = blockIdx.x;
    int t = threadIdx.x;  // 128
    const float* p = in + (long)row * CDIM;
    float v[4], s = 0.f, s2 = 0.f;
    #pragma unroll
    for (int i = 0; i < 4; i++) {
        v[i] = p[t + i * 128];
        s += v[i]; s2 += v[i] * v[i];
    }
    blockRed2(s, s2);
    float mu = s * (1.f / CDIM);
    float var = s2 * (1.f / CDIM) - mu * mu;
    float rstd = rsqrtf(var + 1e-5f);
    float* o = out + (long)row * CDIM;
    #pragma unroll
    for (int i = 0; i < 4; i++) {
        int c = t + i * 128;
        float x = (v[i] - mu) * rstd * w[c] + b[c];
        o[c] = fmaxf(x, 0.f);
    }
}

// ---------------------------------------------------------------------------
// Depthwise causal conv (K=4) + SiLU over x half of xz
// ---------------------------------------------------------------------------
__global__ void dconv_k(const float* __restrict__ w, const float* __restrict__ b) {
    int idx = blockIdx.x * blockDim.x + threadIdx.x;
    if (idx >= CM * CDI) return;
    int d = idx % CDI;
    int row = idx / CDI;
    int l = row % CL;
    const float* xp = g_xz + (long)row * (2 * CDI) + d;
    float4 wv = *(const float4*)(w + d * 4);
    float acc = b[d];
    if (l >= 3) acc = fmaf(xp[-3 * 2 * CDI], wv.x, acc);
    if (l >= 2) acc = fmaf(xp[-2 * 2 * CDI], wv.y, acc);
    if (l >= 1) acc = fmaf(xp[-1 * 2 * CDI], wv.z, acc);
    acc = fmaf(xp[0], wv.w, acc);
    g_xc[idx] = siluf(acc);
}

// ---------------------------------------------------------------------------
// Selective scan: one thread per (b, d); sequential over L=128
// ---------------------------------------------------------------------------
__global__ __launch_bounds__(256) void scan_k(const float* __restrict__ Dskip) {
    int b = blockIdx.x >> 2;
    int d = ((blockIdx.x & 3) << 8) + threadIdx.x;
    float A[CDS], h[CDS];
    #pragma unroll
    for (int n = 0; n < CDS; n++) { A[n] = g_A[d * CDS + n]; h[n] = 0.f; }
    float Dv = Dskip[d];
    long base = (long)b * CL;
    for (int l = 0; l < CL; l++) {
        long r = base + l;
        float dtv = g_dt[r * CDI + d];
        float xv  = g_xc[r * CDI + d];
        const float4* bc = (const float4*)(g_dbc + r * 64 + 32);
        float4 B0 = bc[0], B1 = bc[1], B2 = bc[2], B3 = bc[3];
        float4 C0 = bc[4], C1 = bc[5], C2 = bc[6], C3 = bc[7];
        float Bv[CDS] = {B0.x,B0.y,B0.z,B0.w, B1.x,B1.y,B1.z,B1.w,
                         B2.x,B2.y,B2.z,B2.w, B3.x,B3.y,B3.z,B3.w};
        float Cv[CDS] = {C0.x,C0.y,C0.z,C0.w, C1.x,C1.y,C1.z,C1.w,
                         C2.x,C2.y,C2.z,C2.w, C3.x,C3.y,C3.z,C3.w};
        float dx = dtv * xv;
        float acc = 0.f;
        #pragma unroll
        for (int n = 0; n < CDS; n++) {
            float e = fexp(dtv * A[n]);
            h[n] = fmaf(e, h[n], dx * Bv[n]);
            acc = fmaf(h[n], Cv[n], acc);
        }
        float y = fmaf(xv, Dv, acc);
        float z = g_xz[r * (2 * CDI) + CDI + d];
        g_ys[r * CDI + d] = y * siluf(z);
    }
}

// ---------------------------------------------------------------------------
// Residual + LayerNorm + dot(mlp_a) per row -> coff
// ---------------------------------------------------------------------------
__global__ void final1_k(const float* __restrict__ lnw, const float* __restrict__ lnb,
                         const float* __restrict__ aw, const float* __restrict__ ab)
{
    int row = blockIdx.x;
    int t = threadIdx.x;  // 128
    __shared__ float sv[CDIM];
    float s = 0.f, s2 = 0.f;
    #pragma unroll
    for (int i = 0; i < 4; i++) {
        int c = t + i * 128;
        float v = g_m[(long)row * CDIM + c] + g_fts0[(long)row * CDIM + c];
        sv[c] = v;
        s += v; s2 += v * v;
    }
    blockRed2(s, s2);
    float mu = s * (1.f / CDIM);
    float var = s2 * (1.f / CDIM) - mu * mu;
    float rstd = rsqrtf(var + 1e-5f);
    float dot = 0.f;
    #pragma unroll
    for (int i = 0; i < 4; i++) {
        int c = t + i * 128;
        float x = (sv[c] - mu) * rstd * lnw[c] + lnb[c];
        dot += x * aw[c];
    }
    dot = blockRed1(dot);
    if (t == 0) g_coff[row] = dot + ab[0];
}

__global__ void final2_k(const float* __restrict__ bw, const float* __restrict__ bb,
                         float* __restrict__ out)
{
    int b = blockIdx.x;
    int t = threadIdx.x;  // 128
    float p = g_coff[b * CL + t] * bw[t];
    p = blockRed1(p);
    if (t == 0) out[b] = 1.f / (1.f + __expf(-(p + bb[0])));
}

// ---------------------------------------------------------------------------
// Launch
// ---------------------------------------------------------------------------
extern "C" void kernel_launch(void* const* d_in, const int* in_sizes, int n_in,
                              void* d_out, int out_size)
{
    const float* spt       = (const float*)d_in[0];
    const float* qry       = (const float*)d_in[1];
    const float* conv_w    = (const float*)d_in[2];
    const float* conv_b    = (const float*)d_in[3];
    const float* ln_w      = (const float*)d_in[4];
    const float* ln_b      = (const float*)d_in[5];
    const float* in_proj_w = (const float*)d_in[6];
    const float* conv1d_w  = (const float*)d_in[7];
    const float* conv1d_b  = (const float*)d_in[8];
    const float* x_proj_w  = (const float*)d_in[9];
    const float* dt_proj_w = (const float*)d_in[10];
    const float* dt_proj_b = (const float*)d_in[11];
    const float* A_log     = (const float*)d_in[12];
    const float* D_skip    = (const float*)d_in[13];
    const float* out_proj_w= (const float*)d_in[14];
    const float* mlp_a_w   = (const float*)d_in[15];
    const float* mlp_a_b   = (const float*)d_in[16];
    const float* mlp_b_w   = (const float*)d_in[17];
    const float* mlp_b_b   = (const float*)d_in[18];
    float* out = (float*)d_out;

    float *p_pad, *p_wt, *p_conv, *p_fts0, *p_xz, *p_xc, *p_dbc, *p_dt, *p_ys, *p_m;
    cudaGetSymbolAddress((void**)&p_pad,  g_fts_pad);
    cudaGetSymbolAddress((void**)&p_wt,   g_wt);
    cudaGetSymbolAddress((void**)&p_conv, g_conv);
    cudaGetSymbolAddress((void**)&p_fts0, g_fts0);
    cudaGetSymbolAddress((void**)&p_xz,   g_xz);
    cudaGetSymbolAddress((void**)&p_xc,   g_xc);
    cudaGetSymbolAddress((void**)&p_dbc,  g_dbc);
    cudaGetSymbolAddress((void**)&p_dt,   g_dt);
    cudaGetSymbolAddress((void**)&p_ys,   g_ys);
    cudaGetSymbolAddress((void**)&p_m,    g_m);

    // Prep
    pad_k<<<(CB*130*CDIM + 255)/256, 256>>>(spt, qry);
    wt_k<<<(CDIM*1536 + 255)/256, 256>>>(conv_w);
    a_k<<<(CDI*CDS + 255)/256, 256>>>(A_log);

    // conv (SAME, k=3) as GEMM over padded windows: M=8192 N=512 K=1536
    sgemm_nt<128,128,16,8,8,1><<<dim3(4,64), 256>>>(
        p_pad, p_wt, conv_b, p_conv, 1536, 128, 130L*CDIM, (long)CDIM, 1536, CDIM);
    // LN + ReLU
    ln_relu_k<<<CM, 128>>>(p_conv, ln_w, ln_b, p_fts0);
    // in_proj: M=8192 N=2048 K=512
    sgemm_nt<128,128,16,8,8,0><<<dim3(16,64), 256>>>(
        p_fts0, in_proj_w, nullptr, p_xz, 512, 1<<30, 0L, 512L, 512, 2048);
    // depthwise causal conv + silu
    dconv_k<<<(CM*CDI + 255)/256, 256>>>(conv1d_w, conv1d_b);
    // x_proj: M=8192 N=64 K=1024
    sgemm_nt<128,64,16,8,4,0><<<dim3(1,64), 256>>>(
        p_xc, x_proj_w, nullptr, p_dbc, 1024, 1<<30, 0L, 1024L, 1024, 64);
    // dt: M=8192 N=1024 K=32 (+bias, softplus)
    sgemm_nt<128,128,16,8,8,2><<<dim3(8,64), 256>>>(
        p_dbc, dt_proj_w, dt_proj_b, p_dt, 32, 1<<30, 0L, 64L, 32, CDI);
    // selective scan -> ys = (scan + x*D) * silu(z)
    scan_k<<<CB*4, 256>>>(D_skip);
    // out_proj: M=8192 N=512 K=1024
    sgemm_nt<128,128,16,8,8,0><<<dim3(4,64), 256>>>(
        p_ys, out_proj_w, nullptr, p_m, 1024, 1<<30, 0L, 1024L, 1024, CDIM);
    // residual + LN + mlp_a dot
    final1_k<<<CM, 128>>>(ln_w, ln_b, mlp_a_w, mlp_a_b);
    // mlp_b + sigmoid
    final2_k<<<CB, 128>>>(mlp_b_w, mlp_b_b, out);
}

// round 6
// speedup vs baseline: 1.9008x; 1.9008x over previous
#include <cuda_runtime.h>
#include <cuda_bf16.h>
#include <math.h>
#include <stdint.h>

#define CDIM 512
#define CB   64
#define CL   128
#define CDI  1024
#define CDS  16
#define CM   (CB*CL)

__device__ __align__(16) float g_conv[CM*CDIM];
__device__ __align__(16) float g_fts0[CM*CDIM];
__device__ __align__(16) float g_xz[CM*2*CDI];
__device__ __align__(16) float g_xc[CM*CDI];
__device__ __align__(16) float g_dbc[CM*64];
__device__ __align__(16) float g_dt[CM*CDI];
__device__ __align__(16) float g_m[CM*CDIM];
__device__ __align__(16) float g_A[CDI*CDS];
__device__ __align__(16) float g_coff[CM];
__device__ __align__(16) __nv_bfloat16 g_padh[CB*130*CDIM];
__device__ __align__(16) __nv_bfloat16 g_padl[CB*130*CDIM];
__device__ __align__(16) __nv_bfloat16 g_wth[CDIM*3*CDIM];
__device__ __align__(16) __nv_bfloat16 g_wtl[CDIM*3*CDIM];
__device__ __align__(16) __nv_bfloat16 g_f0h[CM*CDIM];
__device__ __align__(16) __nv_bfloat16 g_f0l[CM*CDIM];
__device__ __align__(16) __nv_bfloat16 g_ipwh[2*CDI*CDIM];
__device__ __align__(16) __nv_bfloat16 g_ipwl[2*CDI*CDIM];
__device__ __align__(16) __nv_bfloat16 g_xch[CM*CDI];
__device__ __align__(16) __nv_bfloat16 g_xcl[CM*CDI];
__device__ __align__(16) __nv_bfloat16 g_xpwh[64*CDI];
__device__ __align__(16) __nv_bfloat16 g_xpwl[64*CDI];
__device__ __align__(16) __nv_bfloat16 g_ysh[CM*CDI];
__device__ __align__(16) __nv_bfloat16 g_ysl[CM*CDI];
__device__ __align__(16) __nv_bfloat16 g_opwh[CDIM*CDI];
__device__ __align__(16) __nv_bfloat16 g_opwl[CDIM*CDI];

__device__ __forceinline__ float softplusf(float x) {
    if (x > 20.f) return x;
    return log1pf(__expf(x));
}
__device__ __forceinline__ float siluf(float x) {
    return x / (1.f + __expf(-x));
}
__device__ __forceinline__ float fexp(float x) {
    x = fmaxf(-80.f, fminf(80.f, x));
    float t = x * 1.4426950408889634f;
    float r = t + 12582912.0f;
    int   n = __float_as_int(r) - 0x4B400000;
    float f = t - (r - 12582912.0f);
    float y = f * 0.6931471805599453f;
    float p = fmaf(y, 8.3333333e-3f, 4.1666667e-2f);
    p = fmaf(y, p, 1.6666667e-1f);
    p = fmaf(y, p, 5.0e-1f);
    p = fmaf(y, p, 1.0f);
    p = fmaf(y, p, 1.0f);
    return __int_as_float(__float_as_int(p) + (n << 23));
}
__device__ __forceinline__ void splitbf(float x, __nv_bfloat16& h, __nv_bfloat16& l) {
    h = __float2bfloat16_rn(x);
    l = __float2bfloat16_rn(x - __bfloat162float(h));
}

__device__ __forceinline__ void blockRed2(float& a, float& b) {
    #pragma unroll
    for (int o = 16; o; o >>= 1) {
        a += __shfl_xor_sync(0xffffffffu, a, o);
        b += __shfl_xor_sync(0xffffffffu, b, o);
    }
    __shared__ float sa[4], sb[4];
    int w = threadIdx.x >> 5;
    if ((threadIdx.x & 31) == 0) { sa[w] = a; sb[w] = b; }
    __syncthreads();
    a = sa[0] + sa[1] + sa[2] + sa[3];
    b = sb[0] + sb[1] + sb[2] + sb[3];
    __syncthreads();
}
__device__ __forceinline__ float blockRed1(float a) {
    #pragma unroll
    for (int o = 16; o; o >>= 1) a += __shfl_xor_sync(0xffffffffu, a, o);
    __shared__ float sc[4];
    int w = threadIdx.x >> 5;
    if ((threadIdx.x & 31) == 0) sc[w] = a;
    __syncthreads();
    float t = sc[0] + sc[1] + sc[2] + sc[3];
    __syncthreads();
    return t;
}

__device__ __forceinline__ uint32_t smem_u32(const void* p) {
    uint32_t a;
    asm("{ .reg .u64 t; cvta.to.shared.u64 t, %1; cvt.u32.u64 %0, t; }" : "=r"(a) : "l"(p));
    return a;
}

#define LDSM4(rr, ad) \
    asm volatile("ldmatrix.sync.aligned.m8n8.x4.shared.b16 {%0,%1,%2,%3}, [%4];" \
        : "=r"((rr)[0]), "=r"((rr)[1]), "=r"((rr)[2]), "=r"((rr)[3]) : "r"(ad))

#define MMA_BF16(cc, aa, bb) \
    asm volatile("mma.sync.aligned.m16n8k16.row.col.f32.bf16.bf16.f32 " \
        "{%0,%1,%2,%3}, {%4,%5,%6,%7}, {%8,%9}, {%0,%1,%2,%3};" \
        : "+f"((cc)[0]), "+f"((cc)[1]), "+f"((cc)[2]), "+f"((cc)[3]) \
        : "r"((aa)[0]), "r"((aa)[1]), "r"((aa)[2]), "r"((aa)[3]), \
          "r"((bb)[0]), "r"((bb)[1]))

// bf16 split-3 tensor GEMM via mma.sync. Block 128 x BN, BK=32, 2-stage cp.async.
// 8 warps: 2(m) x 4(n); warp tile 64 x (BN/4).
template<int BN, int EPI>
__global__ __launch_bounds__(256)
void tmma(const __nv_bfloat16* __restrict__ Ah, const __nv_bfloat16* __restrict__ Al,
          const __nv_bfloat16* __restrict__ Wh, const __nv_bfloat16* __restrict__ Wl,
          const float* __restrict__ bias, float* __restrict__ C,
          int K, int rb, long rbs, long rs, int ldw, int ldc)
{
    constexpr int ASTR  = 80;
    constexpr int ATILE = 128 * ASTR;
    constexpr int BTILE = BN * ASTR;
    constexpr int STAGE = 2 * ATILE + 2 * BTILE;
    constexpr int NCA = 128 * 4, NCB = BN * 4;
    constexpr int TOT = 2 * (NCA + NCB);
    constexpr int WN = BN / 4;
    constexpr int NF = WN / 8;
    extern __shared__ __align__(128) char smem[];

    int tid = threadIdx.x, lane = tid & 31, wid = tid >> 5;
    int wm = wid & 1, wn = wid >> 1;
    int m0 = blockIdx.y * 128, n0 = blockIdx.x * BN;
    uint32_t sbase = smem_u32(smem);

    float c[4][NF][4];
    #pragma unroll
    for (int i = 0; i < 4; i++)
        #pragma unroll
        for (int j = 0; j < NF; j++)
            #pragma unroll
            for (int q = 0; q < 4; q++) c[i][j][q] = 0.f;

    auto loadStage = [&](int s) {
        int p = s & 1, k0 = s * 32;
        uint32_t sb = sbase + p * STAGE;
        #pragma unroll
        for (int it = 0; it < TOT / 256; it++) {
            int ch = tid + it * 256;
            const __nv_bfloat16* g;
            uint32_t so;
            if (ch < 2 * NCA) {
                int cc = (ch < NCA) ? ch : ch - NCA;
                int row = cc >> 2, qo = cc & 3;
                int gm = m0 + row;
                const __nv_bfloat16* base = (ch < NCA) ? Ah : Al;
                g = base + (long)(gm / rb) * rbs + (long)(gm % rb) * rs + k0 + qo * 8;
                so = ((ch < NCA) ? 0u : (uint32_t)ATILE) + row * ASTR + qo * 16;
            } else {
                int ch2 = ch - 2 * NCA;
                int cc = (ch2 < NCB) ? ch2 : ch2 - NCB;
                int row = cc >> 2, qo = cc & 3;
                const __nv_bfloat16* base = (ch2 < NCB) ? Wh : Wl;
                g = base + (long)(n0 + row) * ldw + k0 + qo * 8;
                so = 2 * ATILE + ((ch2 < NCB) ? 0u : (uint32_t)BTILE) + row * ASTR + qo * 16;
            }
            asm volatile("cp.async.cg.shared.global [%0], [%1], 16;"
                         :: "r"(sb + so), "l"((const void*)g));
        }
        asm volatile("cp.async.commit_group;" ::: "memory");
    };

    auto compStage = [&](int p) {
        uint32_t sb = sbase + p * STAGE;
        int mat = lane >> 3, r8 = lane & 7;
        #pragma unroll
        for (int kf = 0; kf < 2; kf++) {
            uint32_t ah[4][4], al[4][4], bh[NF][2], bl[NF][2];
            #pragma unroll
            for (int mf = 0; mf < 4; mf++) {
                uint32_t ad = sb + (uint32_t)((wm * 64 + mf * 16 + ((mat & 1) << 3) + r8) * ASTR
                                              + kf * 32 + ((mat >> 1) << 4));
                LDSM4(ah[mf], ad);
                LDSM4(al[mf], ad + ATILE);
            }
            #pragma unroll
            for (int pp = 0; pp < NF / 2; pp++) {
                uint32_t bd = sb + 2 * ATILE
                            + (uint32_t)((wn * WN + pp * 16 + ((mat >> 1) << 3) + r8) * ASTR
                                         + kf * 32 + ((mat & 1) << 4));
                uint32_t t[4];
                LDSM4(t, bd);
                bh[2*pp][0] = t[0]; bh[2*pp][1] = t[1];
                bh[2*pp+1][0] = t[2]; bh[2*pp+1][1] = t[3];
                LDSM4(t, bd + BTILE);
                bl[2*pp][0] = t[0]; bl[2*pp][1] = t[1];
                bl[2*pp+1][0] = t[2]; bl[2*pp+1][1] = t[3];
            }
            #pragma unroll
            for (int mf = 0; mf < 4; mf++)
                #pragma unroll
                for (int nf = 0; nf < NF; nf++) {
                    MMA_BF16(c[mf][nf], ah[mf], bh[nf]);
                    MMA_BF16(c[mf][nf], al[mf], bh[nf]);
                    MMA_BF16(c[mf][nf], ah[mf], bl[nf]);
                }
        }
    };

    int S = K >> 5;
    loadStage(0);
    for (int s = 0; s < S; s++) {
        if (s + 1 < S) {
            loadStage(s + 1);
            asm volatile("cp.async.wait_group 1;" ::: "memory");
        } else {
            asm volatile("cp.async.wait_group 0;" ::: "memory");
        }
        __syncthreads();
        compStage(s & 1);
        __syncthreads();
    }

    #pragma unroll
    for (int mf = 0; mf < 4; mf++) {
        int gm0 = m0 + wm * 64 + mf * 16 + (lane >> 2);
        #pragma unroll
        for (int nf = 0; nf < NF; nf++) {
            int gn = n0 + wn * WN + nf * 8 + (lane & 3) * 2;
            float2 v0 = make_float2(c[mf][nf][0], c[mf][nf][1]);
            float2 v1 = make_float2(c[mf][nf][2], c[mf][nf][3]);
            if (EPI == 1) {
                float b0 = bias[gn], b1 = bias[gn + 1];
                v0.x += b0; v0.y += b1; v1.x += b0; v1.y += b1;
            }
            *(float2*)(C + (long)gm0 * ldc + gn) = v0;
            *(float2*)(C + (long)(gm0 + 8) * ldc + gn) = v1;
        }
    }
}

// fp32 GEMM (tiny dt projection, K=32)
template<int BM, int BN, int BK, int TM, int TN, int EPI>
__global__ __launch_bounds__((BM/TM)*(BN/TN))
void sgemm_nt(const float* __restrict__ A, const float* __restrict__ W,
              const float* __restrict__ bias, float* __restrict__ C,
              int K, int rb, long rbs, long rs, int ldw, int ldc)
{
    constexpr int TX = BN / TN, TY = BM / TM, NT = TX * TY;
    constexpr int K4 = BK / 4;
    constexpr int ROWS_PER = NT / K4;
    static_assert(NT == 256, "thread count");

    __shared__ __align__(16) float As[BK][BM];
    __shared__ __align__(16) float Ws[BK][BN];

    int tid = threadIdx.x;
    int m0 = blockIdx.y * BM, n0 = blockIdx.x * BN;
    int tx = tid % TX, ty = tid / TX;
    int arow = tid / K4, ac4 = (tid % K4) * 4;

    float acc[TM][TN];
    #pragma unroll
    for (int i = 0; i < TM; i++)
        #pragma unroll
        for (int j = 0; j < TN; j++) acc[i][j] = 0.f;

    for (int k0 = 0; k0 < K; k0 += BK) {
        #pragma unroll
        for (int r = arow; r < BM; r += ROWS_PER) {
            int grow = m0 + r;
            const float* ap = A + (long)(grow / rb) * rbs + (long)(grow % rb) * rs + k0 + ac4;
            float4 v = *(const float4*)ap;
            As[ac4 + 0][r] = v.x; As[ac4 + 1][r] = v.y;
            As[ac4 + 2][r] = v.z; As[ac4 + 3][r] = v.w;
        }
        #pragma unroll
        for (int r = arow; r < BN; r += ROWS_PER) {
            const float* wp = W + (long)(n0 + r) * ldw + k0 + ac4;
            float4 v = *(const float4*)wp;
            Ws[ac4 + 0][r] = v.x; Ws[ac4 + 1][r] = v.y;
            Ws[ac4 + 2][r] = v.z; Ws[ac4 + 3][r] = v.w;
        }
        __syncthreads();
        #pragma unroll
        for (int k = 0; k < BK; k++) {
            float a[TM], wv[TN];
            #pragma unroll
            for (int i = 0; i < TM; i += 4) {
                float4 t = *(const float4*)&As[k][ty * TM + i];
                a[i] = t.x; a[i+1] = t.y; a[i+2] = t.z; a[i+3] = t.w;
            }
            #pragma unroll
            for (int j = 0; j < TN; j += 4) {
                float4 t = *(const float4*)&Ws[k][tx * TN + j];
                wv[j] = t.x; wv[j+1] = t.y; wv[j+2] = t.z; wv[j+3] = t.w;
            }
            #pragma unroll
            for (int i = 0; i < TM; i++)
                #pragma unroll
                for (int j = 0; j < TN; j++)
                    acc[i][j] = fmaf(a[i], wv[j], acc[i][j]);
        }
        __syncthreads();
    }

    #pragma unroll
    for (int i = 0; i < TM; i++) {
        int gm = m0 + ty * TM + i;
        float* cp = C + (long)gm * ldc + n0 + tx * TN;
        #pragma unroll
        for (int j = 0; j < TN; j += 4) {
            float4 v;
            float e0 = acc[i][j], e1 = acc[i][j+1], e2 = acc[i][j+2], e3 = acc[i][j+3];
            if (EPI >= 1) {
                int gn = n0 + tx * TN + j;
                e0 += bias[gn]; e1 += bias[gn+1]; e2 += bias[gn+2]; e3 += bias[gn+3];
            }
            if (EPI == 2) {
                e0 = softplusf(e0); e1 = softplusf(e1);
                e2 = softplusf(e2); e3 = softplusf(e3);
            }
            v.x = e0; v.y = e1; v.z = e2; v.w = e3;
            *(float4*)(cp + j) = v;
        }
    }
}

__global__ void pad_k(const float* __restrict__ spt, const float* __restrict__ qry) {
    int idx = blockIdx.x * blockDim.x + threadIdx.x;
    if (idx >= CB * 130 * CDIM) return;
    int b = idx / (130 * CDIM);
    int r = idx % (130 * CDIM);
    int l = r / CDIM;
    int c = r % CDIM;
    float v = 0.f;
    if (l >= 1 && l <= 128) {
        int ll = l - 1;
        v = (ll < 64) ? spt[b * 32768 + ll * CDIM + c]
                      : qry[b * 32768 + (ll - 64) * CDIM + c];
    }
    splitbf(v, g_padh[idx], g_padl[idx]);
}
__global__ void wt_k(const float* __restrict__ cw) {
    int idx = blockIdx.x * blockDim.x + threadIdx.x;
    if (idx >= CDIM * 1536) return;
    int co = idx / 1536;
    int r  = idx % 1536;
    int k  = r / CDIM;
    int ci = r % CDIM;
    splitbf(cw[(co * CDIM + ci) * 3 + k], g_wth[idx], g_wtl[idx]);
}
__global__ void wcvt_k(const float* __restrict__ w, __nv_bfloat16* __restrict__ h,
                       __nv_bfloat16* __restrict__ l, int n) {
    int i = blockIdx.x * blockDim.x + threadIdx.x;
    if (i >= n) return;
    splitbf(w[i], h[i], l[i]);
}
__global__ void a_k(const float* __restrict__ alog) {
    int idx = blockIdx.x * blockDim.x + threadIdx.x;
    if (idx >= CDI * CDS) return;
    g_A[idx] = -expf(alog[idx]);
}

__global__ void ln_relu_k(const float* __restrict__ in, const float* __restrict__ w,
                          const float* __restrict__ b)
{
    int row = blockIdx.x;
    int t = threadIdx.x;
    const float* p = in + (long)row * CDIM;
    float v[4], s = 0.f, s2 = 0.f;
    #pragma unroll
    for (int i = 0; i < 4; i++) {
        v[i] = p[t + i * 128];
        s += v[i]; s2 += v[i] * v[i];
    }
    blockRed2(s, s2);
    float mu = s * (1.f / CDIM);
    float var = s2 * (1.f / CDIM) - mu * mu;
    float rstd = rsqrtf(var + 1e-5f);
    #pragma unroll
    for (int i = 0; i < 4; i++) {
        int c = t + i * 128;
        long o = (long)row * CDIM + c;
        float x = (v[i] - mu) * rstd * w[c] + b[c];
        x = fmaxf(x, 0.f);
        g_fts0[o] = x;
        splitbf(x, g_f0h[o], g_f0l[o]);
    }
}

__global__ void dconv_k(const float* __restrict__ w, const float* __restrict__ b) {
    int idx = blockIdx.x * blockDim.x + threadIdx.x;
    if (idx >= CM * CDI) return;
    int d = idx % CDI;
    int row = idx / CDI;
    int l = row % CL;
    const float* xp = g_xz + (long)row * (2 * CDI) + d;
    float4 wv = *(const float4*)(w + d * 4);
    float acc = b[d];
    if (l >= 3) acc = fmaf(xp[-3 * 2 * CDI], wv.x, acc);
    if (l >= 2) acc = fmaf(xp[-2 * 2 * CDI], wv.y, acc);
    if (l >= 1) acc = fmaf(xp[-1 * 2 * CDI], wv.z, acc);
    acc = fmaf(xp[0], wv.w, acc);
    float xv = siluf(acc);
    g_xc[idx] = xv;
    splitbf(xv, g_xch[idx], g_xcl[idx]);
}

__global__ __launch_bounds__(256) void scan_k(const float* __restrict__ Dskip) {
    int b = blockIdx.x >> 2;
    int d = ((blockIdx.x & 3) << 8) + threadIdx.x;
    float A[CDS], h[CDS];
    #pragma unroll
    for (int n = 0; n < CDS; n++) { A[n] = g_A[d * CDS + n]; h[n] = 0.f; }
    float Dv = Dskip[d];
    long base = (long)b * CL;
    for (int l = 0; l < CL; l++) {
        long r = base + l;
        float dtv = g_dt[r * CDI + d];
        float xv  = g_xc[r * CDI + d];
        const float4* bc = (const float4*)(g_dbc + r * 64 + 32);
        float4 B0 = bc[0], B1 = bc[1], B2 = bc[2], B3 = bc[3];
        float4 C0 = bc[4], C1 = bc[5], C2 = bc[6], C3 = bc[7];
        float Bv[CDS] = {B0.x,B0.y,B0.z,B0.w, B1.x,B1.y,B1.z,B1.w,
                         B2.x,B2.y,B2.z,B2.w, B3.x,B3.y,B3.z,B3.w};
        float Cv[CDS] = {C0.x,C0.y,C0.z,C0.w, C1.x,C1.y,C1.z,C1.w,
                         C2.x,C2.y,C2.z,C2.w, C3.x,C3.y,C3.z,C3.w};
        float dx = dtv * xv;
        float acc = 0.f;
        #pragma unroll
        for (int n = 0; n < CDS; n++) {
            float e = fexp(dtv * A[n]);
            h[n] = fmaf(e, h[n], dx * Bv[n]);
            acc = fmaf(h[n], Cv[n], acc);
        }
        float y = fmaf(xv, Dv, acc);
        float z = g_xz[r * (2 * CDI) + CDI + d];
        float o = y * siluf(z);
        splitbf(o, g_ysh[r * CDI + d], g_ysl[r * CDI + d]);
    }
}

__global__ void final1_k(const float* __restrict__ lnw, const float* __restrict__ lnb,
                         const float* __restrict__ aw, const float* __restrict__ ab)
{
    int row = blockIdx.x;
    int t = threadIdx.x;
    __shared__ float sv[CDIM];
    float s = 0.f, s2 = 0.f;
    #pragma unroll
    for (int i = 0; i < 4; i++) {
        int c = t + i * 128;
        float v = g_m[(long)row * CDIM + c] + g_fts0[(long)row * CDIM + c];
        sv[c] = v;
        s += v; s2 += v * v;
    }
    blockRed2(s, s2);
    float mu = s * (1.f / CDIM);
    float var = s2 * (1.f / CDIM) - mu * mu;
    float rstd = rsqrtf(var + 1e-5f);
    float dot = 0.f;
    #pragma unroll
    for (int i = 0; i < 4; i++) {
        int c = t + i * 128;
        float x = (sv[c] - mu) * rstd * lnw[c] + lnb[c];
        dot += x * aw[c];
    }
    dot = blockRed1(dot);
    if (t == 0) g_coff[row] = dot + ab[0];
}

__global__ void final2_k(const float* __restrict__ bw, const float* __restrict__ bb,
                         float* __restrict__ out)
{
    int b = blockIdx.x;
    int t = threadIdx.x;
    float p = g_coff[b * CL + t] * bw[t];
    p = blockRed1(p);
    if (t == 0) out[b] = 1.f / (1.f + __expf(-(p + bb[0])));
}

extern "C" void kernel_launch(void* const* d_in, const int* in_sizes, int n_in,
                              void* d_out, int out_size)
{
    const float* spt       = (const float*)d_in[0];
    const float* qry       = (const float*)d_in[1];
    const float* conv_w    = (const float*)d_in[2];
    const float* conv_b    = (const float*)d_in[3];
    const float* ln_w      = (const float*)d_in[4];
    const float* ln_b      = (const float*)d_in[5];
    const float* in_proj_w = (const float*)d_in[6];
    const float* conv1d_w  = (const float*)d_in[7];
    const float* conv1d_b  = (const float*)d_in[8];
    const float* x_proj_w  = (const float*)d_in[9];
    const float* dt_proj_w = (const float*)d_in[10];
    const float* dt_proj_b = (const float*)d_in[11];
    const float* A_log     = (const float*)d_in[12];
    const float* D_skip    = (const float*)d_in[13];
    const float* out_proj_w= (const float*)d_in[14];
    const float* mlp_a_w   = (const float*)d_in[15];
    const float* mlp_a_b   = (const float*)d_in[16];
    const float* mlp_b_w   = (const float*)d_in[17];
    const float* mlp_b_b   = (const float*)d_in[18];
    float* out = (float*)d_out;

    float *p_conv, *p_dbc, *p_dt, *p_m, *p_xz;
    cudaGetSymbolAddress((void**)&p_conv, g_conv);
    cudaGetSymbolAddress((void**)&p_dbc,  g_dbc);
    cudaGetSymbolAddress((void**)&p_dt,   g_dt);
    cudaGetSymbolAddress((void**)&p_m,    g_m);
    cudaGetSymbolAddress((void**)&p_xz,   g_xz);
    __nv_bfloat16 *ph_pad, *pl_pad, *ph_wt, *pl_wt, *ph_f0, *pl_f0, *ph_ipw, *pl_ipw;
    __nv_bfloat16 *ph_xc, *pl_xc, *ph_xpw, *pl_xpw, *ph_ys, *pl_ys, *ph_opw, *pl_opw;
    cudaGetSymbolAddress((void**)&ph_pad, g_padh); cudaGetSymbolAddress((void**)&pl_pad, g_padl);
    cudaGetSymbolAddress((void**)&ph_wt,  g_wth);  cudaGetSymbolAddress((void**)&pl_wt,  g_wtl);
    cudaGetSymbolAddress((void**)&ph_f0,  g_f0h);  cudaGetSymbolAddress((void**)&pl_f0,  g_f0l);
    cudaGetSymbolAddress((void**)&ph_ipw, g_ipwh); cudaGetSymbolAddress((void**)&pl_ipw, g_ipwl);
    cudaGetSymbolAddress((void**)&ph_xc,  g_xch);  cudaGetSymbolAddress((void**)&pl_xc,  g_xcl);
    cudaGetSymbolAddress((void**)&ph_xpw, g_xpwh); cudaGetSymbolAddress((void**)&pl_xpw, g_xpwl);
    cudaGetSymbolAddress((void**)&ph_ys,  g_ysh);  cudaGetSymbolAddress((void**)&pl_ys,  g_ysl);
    cudaGetSymbolAddress((void**)&ph_opw, g_opwh); cudaGetSymbolAddress((void**)&pl_opw, g_opwl);

    const int SM128 = 2 * (2 * 128 * 80 + 2 * 128 * 80);  // 81920 B
    const int SM64  = 2 * (2 * 128 * 80 + 2 * 64 * 80);   // 61440 B
    cudaFuncSetAttribute(tmma<128,1>, cudaFuncAttributeMaxDynamicSharedMemorySize, SM128);
    cudaFuncSetAttribute(tmma<128,0>, cudaFuncAttributeMaxDynamicSharedMemorySize, SM128);
    cudaFuncSetAttribute(tmma<64,0>,  cudaFuncAttributeMaxDynamicSharedMemorySize, SM64);

    pad_k<<<(CB*130*CDIM + 255)/256, 256>>>(spt, qry);
    wt_k<<<(CDIM*1536 + 255)/256, 256>>>(conv_w);
    a_k<<<(CDI*CDS + 255)/256, 256>>>(A_log);
    wcvt_k<<<(2*CDI*CDIM + 255)/256, 256>>>(in_proj_w, ph_ipw, pl_ipw, 2*CDI*CDIM);
    wcvt_k<<<(64*CDI + 255)/256, 256>>>(x_proj_w, ph_xpw, pl_xpw, 64*CDI);
    wcvt_k<<<(CDIM*CDI + 255)/256, 256>>>(out_proj_w, ph_opw, pl_opw, CDIM*CDI);

    // conv (SAME, k=3) as GEMM: M=8192 N=512 K=1536
    tmma<128,1><<<dim3(4,64), 256, SM128>>>(
        ph_pad, pl_pad, ph_wt, pl_wt, conv_b, p_conv,
        1536, 128, 130L*CDIM, (long)CDIM, 1536, CDIM);
    ln_relu_k<<<CM, 128>>>(p_conv, ln_w, ln_b);
    // in_proj: M=8192 N=2048 K=512
    tmma<128,0><<<dim3(16,64), 256, SM128>>>(
        ph_f0, pl_f0, ph_ipw, pl_ipw, nullptr, p_xz,
        512, 1<<30, 0L, 512L, 512, 2048);
    dconv_k<<<(CM*CDI + 255)/256, 256>>>(conv1d_w, conv1d_b);
    // x_proj: M=8192 N=64 K=1024
    tmma<64,0><<<dim3(1,64), 256, SM64>>>(
        ph_xc, pl_xc, ph_xpw, pl_xpw, nullptr, p_dbc,
        1024, 1<<30, 0L, 1024L, 1024, 64);
    // dt: M=8192 N=1024 K=32 (+bias, softplus)
    sgemm_nt<128,128,16,8,8,2><<<dim3(8,64), 256>>>(
        p_dbc, dt_proj_w, dt_proj_b, p_dt, 32, 1<<30, 0L, 64L, 32, CDI);
    scan_k<<<CB*4, 256>>>(D_skip);
    // out_proj: M=8192 N=512 K=1024
    tmma<128,0><<<dim3(4,64), 256, SM128>>>(
        ph_ys, pl_ys, ph_opw, pl_opw, nullptr, p_m,
        1024, 1<<30, 0L, 1024L, 1024, CDIM);
    final1_k<<<CM, 128>>>(ln_w, ln_b, mlp_a_w, mlp_a_b);
    final2_k<<<CB, 128>>>(mlp_b_w, mlp_b_b, out);
}

// round 8
// speedup vs baseline: 2.5784x; 1.3565x over previous
#include <cuda_runtime.h>
#include <cuda_fp16.h>
#include <math.h>
#include <stdint.h>

#define CDIM 512
#define CB   64
#define CL   128
#define CDI  1024
#define CDS  16
#define CM   (CB*CL)

// fp32 intermediates
__device__ __align__(16) float g_conv[CM*CDIM];
__device__ __align__(16) float g_fts0[CM*CDIM];
__device__ __align__(16) float g_xz[CM*2*CDI];
__device__ __align__(16) float g_xc[CM*CDI];
__device__ __align__(16) float g_dbc[CM*64];
__device__ __align__(16) float g_dt[CM*CDI];
__device__ __align__(16) float g_m[CM*CDIM];
__device__ __align__(16) float g_A[CDI*CDS];
__device__ __align__(16) float g_coff[CM];
// fp16 GEMM operands
__device__ __align__(16) __half g_padh[CB*130*CDIM];
__device__ __align__(16) __half g_wth[CDIM*3*CDIM];
__device__ __align__(16) __half g_f0h[CM*CDIM];
__device__ __align__(16) __half g_ipwh[2*CDI*CDIM];
__device__ __align__(16) __half g_xch[CM*CDI];
__device__ __align__(16) __half g_xpwh[64*CDI];
__device__ __align__(16) __half g_ysh[CM*CDI];
__device__ __align__(16) __half g_opwh[CDIM*CDI];

__device__ __forceinline__ float softplusf(float x) {
    if (x > 20.f) return x;
    return log1pf(__expf(x));
}
__device__ __forceinline__ float siluf(float x) {
    return x / (1.f + __expf(-x));
}
// FFMA-only fast exp (keeps MUFU off the scan's critical path)
__device__ __forceinline__ float fexp(float x) {
    x = fmaxf(-80.f, fminf(80.f, x));
    float t = x * 1.4426950408889634f;
    float r = t + 12582912.0f;
    int   n = __float_as_int(r) - 0x4B400000;
    float f = t - (r - 12582912.0f);
    float y = f * 0.6931471805599453f;
    float p = fmaf(y, 8.3333333e-3f, 4.1666667e-2f);
    p = fmaf(y, p, 1.6666667e-1f);
    p = fmaf(y, p, 5.0e-1f);
    p = fmaf(y, p, 1.0f);
    p = fmaf(y, p, 1.0f);
    return __int_as_float(__float_as_int(p) + (n << 23));
}

__device__ __forceinline__ void blockRed2(float& a, float& b) {
    #pragma unroll
    for (int o = 16; o; o >>= 1) {
        a += __shfl_xor_sync(0xffffffffu, a, o);
        b += __shfl_xor_sync(0xffffffffu, b, o);
    }
    __shared__ float sa[4], sb[4];
    int w = threadIdx.x >> 5;
    if ((threadIdx.x & 31) == 0) { sa[w] = a; sb[w] = b; }
    __syncthreads();
    a = sa[0] + sa[1] + sa[2] + sa[3];
    b = sb[0] + sb[1] + sb[2] + sb[3];
    __syncthreads();
}
__device__ __forceinline__ float blockRed1(float a) {
    #pragma unroll
    for (int o = 16; o; o >>= 1) a += __shfl_xor_sync(0xffffffffu, a, o);
    __shared__ float sc[4];
    int w = threadIdx.x >> 5;
    if ((threadIdx.x & 31) == 0) sc[w] = a;
    __syncthreads();
    float t = sc[0] + sc[1] + sc[2] + sc[3];
    __syncthreads();
    return t;
}

__device__ __forceinline__ uint32_t smem_u32(const void* p) {
    uint32_t a;
    asm("{ .reg .u64 t; cvta.to.shared.u64 t, %1; cvt.u32.u64 %0, t; }" : "=r"(a) : "l"(p));
    return a;
}

#define LDSM4(rr, ad) \
    asm volatile("ldmatrix.sync.aligned.m8n8.x4.shared.b16 {%0,%1,%2,%3}, [%4];" \
        : "=r"((rr)[0]), "=r"((rr)[1]), "=r"((rr)[2]), "=r"((rr)[3]) : "r"(ad))

#define MMA_F16(cc, aa, bb) \
    asm volatile("mma.sync.aligned.m16n8k16.row.col.f32.f16.f16.f32 " \
        "{%0,%1,%2,%3}, {%4,%5,%6,%7}, {%8,%9}, {%0,%1,%2,%3};" \
        : "+f"((cc)[0]), "+f"((cc)[1]), "+f"((cc)[2]), "+f"((cc)[3]) \
        : "r"((aa)[0]), "r"((aa)[1]), "r"((aa)[2]), "r"((aa)[3]), \
          "r"((bb)[0]), "r"((bb)[1]))

// fp16 tensor GEMM via mma.sync. Block 128 x BN, BK=32, 2-stage cp.async.
// 8 warps: 2(m) x 4(n); warp tile 64 x (BN/4).
// C[m][n] = sum_k A[m][k]*W[n][k]; A_row(m) = A + (m/rb)*rbs + (m%rb)*rs
// EPI: 0 none, 1 +bias
template<int BN, int EPI>
__global__ __launch_bounds__(256)
void tmma(const __half* __restrict__ Ah, const __half* __restrict__ Wh,
          const float* __restrict__ bias, float* __restrict__ C,
          int K, int rb, long rbs, long rs, int ldw, int ldc)
{
    constexpr int ASTR  = 80;             // 64B data + 16B pad per smem row
    constexpr int ATILE = 128 * ASTR;
    constexpr int BTILE = BN * ASTR;
    constexpr int STAGE = ATILE + BTILE;
    constexpr int NCA = 128 * 4, NCB = BN * 4;   // 16B chunks
    constexpr int TOT = NCA + NCB;
    constexpr int WN = BN / 4;
    constexpr int NF = WN / 8;
    extern __shared__ __align__(128) char smem[];

    int tid = threadIdx.x, lane = tid & 31, wid = tid >> 5;
    int wm = wid & 1, wn = wid >> 1;
    int m0 = blockIdx.y * 128, n0 = blockIdx.x * BN;
    uint32_t sbase = smem_u32(smem);

    float c[4][NF][4];
    #pragma unroll
    for (int i = 0; i < 4; i++)
        #pragma unroll
        for (int j = 0; j < NF; j++)
            #pragma unroll
            for (int q = 0; q < 4; q++) c[i][j][q] = 0.f;

    auto loadStage = [&](int s) {
        int p = s & 1, k0 = s * 32;
        uint32_t sb = sbase + p * STAGE;
        #pragma unroll
        for (int it = 0; it < TOT / 256; it++) {
            int ch = tid + it * 256;
            const __half* g;
            uint32_t so;
            if (ch < NCA) {
                int row = ch >> 2, qo = ch & 3;
                int gm = m0 + row;
                g = Ah + (long)(gm / rb) * rbs + (long)(gm % rb) * rs + k0 + qo * 8;
                so = row * ASTR + qo * 16;
            } else {
                int cc = ch - NCA;
                int row = cc >> 2, qo = cc & 3;
                g = Wh + (long)(n0 + row) * ldw + k0 + qo * 8;
                so = ATILE + row * ASTR + qo * 16;
            }
            asm volatile("cp.async.cg.shared.global [%0], [%1], 16;"
                         :: "r"(sb + so), "l"((const void*)g));
        }
        asm volatile("cp.async.commit_group;" ::: "memory");
    };

    auto compStage = [&](int p) {
        uint32_t sb = sbase + p * STAGE;
        int mat = lane >> 3, r8 = lane & 7;
        #pragma unroll
        for (int kf = 0; kf < 2; kf++) {
            uint32_t ah[4][4], bh[NF][2];
            #pragma unroll
            for (int mf = 0; mf < 4; mf++) {
                uint32_t ad = sb + (uint32_t)((wm * 64 + mf * 16 + ((mat & 1) << 3) + r8) * ASTR
                                              + kf * 32 + ((mat >> 1) << 4));
                LDSM4(ah[mf], ad);
            }
            #pragma unroll
            for (int pp = 0; pp < NF / 2; pp++) {
                uint32_t bd = sb + ATILE
                            + (uint32_t)((wn * WN + pp * 16 + ((mat >> 1) << 3) + r8) * ASTR
                                         + kf * 32 + ((mat & 1) << 4));
                uint32_t t[4];
                LDSM4(t, bd);
                bh[2*pp][0] = t[0]; bh[2*pp][1] = t[1];
                bh[2*pp+1][0] = t[2]; bh[2*pp+1][1] = t[3];
            }
            #pragma unroll
            for (int mf = 0; mf < 4; mf++)
                #pragma unroll
                for (int nf = 0; nf < NF; nf++)
                    MMA_F16(c[mf][nf], ah[mf], bh[nf]);
        }
    };

    int S = K >> 5;
    loadStage(0);
    for (int s = 0; s < S; s++) {
        if (s + 1 < S) {
            loadStage(s + 1);
            asm volatile("cp.async.wait_group 1;" ::: "memory");
        } else {
            asm volatile("cp.async.wait_group 0;" ::: "memory");
        }
        __syncthreads();
        compStage(s & 1);
        __syncthreads();
    }

    #pragma unroll
    for (int mf = 0; mf < 4; mf++) {
        int gm0 = m0 + wm * 64 + mf * 16 + (lane >> 2);
        #pragma unroll
        for (int nf = 0; nf < NF; nf++) {
            int gn = n0 + wn * WN + nf * 8 + (lane & 3) * 2;
            float2 v0 = make_float2(c[mf][nf][0], c[mf][nf][1]);
            float2 v1 = make_float2(c[mf][nf][2], c[mf][nf][3]);
            if (EPI == 1) {
                float b0 = bias[gn], b1 = bias[gn + 1];
                v0.x += b0; v0.y += b1; v1.x += b0; v1.y += b1;
            }
            *(float2*)(C + (long)gm0 * ldc + gn) = v0;
            *(float2*)(C + (long)(gm0 + 8) * ldc + gn) = v1;
        }
    }
}

// fp32 GEMM (tiny dt projection, K=32)
template<int BM, int BN, int BK, int TM, int TN, int EPI>
__global__ __launch_bounds__((BM/TM)*(BN/TN))
void sgemm_nt(const float* __restrict__ A, const float* __restrict__ W,
              const float* __restrict__ bias, float* __restrict__ C,
              int K, int rb, long rbs, long rs, int ldw, int ldc)
{
    constexpr int TX = BN / TN, TY = BM / TM, NT = TX * TY;
    constexpr int K4 = BK / 4;
    constexpr int ROWS_PER = NT / K4;
    static_assert(NT == 256, "thread count");

    __shared__ __align__(16) float As[BK][BM];
    __shared__ __align__(16) float Ws[BK][BN];

    int tid = threadIdx.x;
    int m0 = blockIdx.y * BM, n0 = blockIdx.x * BN;
    int tx = tid % TX, ty = tid / TX;
    int arow = tid / K4, ac4 = (tid % K4) * 4;

    float acc[TM][TN];
    #pragma unroll
    for (int i = 0; i < TM; i++)
        #pragma unroll
        for (int j = 0; j < TN; j++) acc[i][j] = 0.f;

    for (int k0 = 0; k0 < K; k0 += BK) {
        #pragma unroll
        for (int r = arow; r < BM; r += ROWS_PER) {
            int grow = m0 + r;
            const float* ap = A + (long)(grow / rb) * rbs + (long)(grow % rb) * rs + k0 + ac4;
            float4 v = *(const float4*)ap;
            As[ac4 + 0][r] = v.x; As[ac4 + 1][r] = v.y;
            As[ac4 + 2][r] = v.z; As[ac4 + 3][r] = v.w;
        }
        #pragma unroll
        for (int r = arow; r < BN; r += ROWS_PER) {
            const float* wp = W + (long)(n0 + r) * ldw + k0 + ac4;
            float4 v = *(const float4*)wp;
            Ws[ac4 + 0][r] = v.x; Ws[ac4 + 1][r] = v.y;
            Ws[ac4 + 2][r] = v.z; Ws[ac4 + 3][r] = v.w;
        }
        __syncthreads();
        #pragma unroll
        for (int k = 0; k < BK; k++) {
            float a[TM], wv[TN];
            #pragma unroll
            for (int i = 0; i < TM; i += 4) {
                float4 t = *(const float4*)&As[k][ty * TM + i];
                a[i] = t.x; a[i+1] = t.y; a[i+2] = t.z; a[i+3] = t.w;
            }
            #pragma unroll
            for (int j = 0; j < TN; j += 4) {
                float4 t = *(const float4*)&Ws[k][tx * TN + j];
                wv[j] = t.x; wv[j+1] = t.y; wv[j+2] = t.z; wv[j+3] = t.w;
            }
            #pragma unroll
            for (int i = 0; i < TM; i++)
                #pragma unroll
                for (int j = 0; j < TN; j++)
                    acc[i][j] = fmaf(a[i], wv[j], acc[i][j]);
        }
        __syncthreads();
    }

    #pragma unroll
    for (int i = 0; i < TM; i++) {
        int gm = m0 + ty * TM + i;
        float* cp = C + (long)gm * ldc + n0 + tx * TN;
        #pragma unroll
        for (int j = 0; j < TN; j += 4) {
            float4 v;
            float e0 = acc[i][j], e1 = acc[i][j+1], e2 = acc[i][j+2], e3 = acc[i][j+3];
            if (EPI >= 1) {
                int gn = n0 + tx * TN + j;
                e0 += bias[gn]; e1 += bias[gn+1]; e2 += bias[gn+2]; e3 += bias[gn+3];
            }
            if (EPI == 2) {
                e0 = softplusf(e0); e1 = softplusf(e1);
                e2 = softplusf(e2); e3 = softplusf(e3);
            }
            v.x = e0; v.y = e1; v.z = e2; v.w = e3;
            *(float4*)(cp + j) = v;
        }
    }
}

__global__ void pad_k(const float* __restrict__ spt, const float* __restrict__ qry) {
    int idx = blockIdx.x * blockDim.x + threadIdx.x;
    if (idx >= CB * 130 * CDIM) return;
    int b = idx / (130 * CDIM);
    int r = idx % (130 * CDIM);
    int l = r / CDIM;
    int c = r % CDIM;
    float v = 0.f;
    if (l >= 1 && l <= 128) {
        int ll = l - 1;
        v = (ll < 64) ? spt[b * 32768 + ll * CDIM + c]
                      : qry[b * 32768 + (ll - 64) * CDIM + c];
    }
    g_padh[idx] = __float2half_rn(v);
}
__global__ void wt_k(const float* __restrict__ cw) {
    int idx = blockIdx.x * blockDim.x + threadIdx.x;
    if (idx >= CDIM * 1536) return;
    int co = idx / 1536;
    int r  = idx % 1536;
    int k  = r / CDIM;
    int ci = r % CDIM;
    g_wth[idx] = __float2half_rn(cw[(co * CDIM + ci) * 3 + k]);
}
__global__ void wcvt_k(const float* __restrict__ w, __half* __restrict__ h, int n) {
    int i = blockIdx.x * blockDim.x + threadIdx.x;
    if (i >= n) return;
    h[i] = __float2half_rn(w[i]);
}
__global__ void a_k(const float* __restrict__ alog) {
    int idx = blockIdx.x * blockDim.x + threadIdx.x;
    if (idx >= CDI * CDS) return;
    g_A[idx] = -expf(alog[idx]);
}

__global__ void ln_relu_k(const float* __restrict__ in, const float* __restrict__ w,
                          const float* __restrict__ b)
{
    int row = blockIdx.x;
    int t = threadIdx.x;
    const float* p = in + (long)row * CDIM;
    float v[4], s = 0.f, s2 = 0.f;
    #pragma unroll
    for (int i = 0; i < 4; i++) {
        v[i] = p[t + i * 128];
        s += v[i]; s2 += v[i] * v[i];
    }
    blockRed2(s, s2);
    float mu = s * (1.f / CDIM);
    float var = s2 * (1.f / CDIM) - mu * mu;
    float rstd = rsqrtf(var + 1e-5f);
    #pragma unroll
    for (int i = 0; i < 4; i++) {
        int c = t + i * 128;
        long o = (long)row * CDIM + c;
        float x = (v[i] - mu) * rstd * w[c] + b[c];
        x = fmaxf(x, 0.f);
        g_fts0[o] = x;
        g_f0h[o] = __float2half_rn(x);
    }
}

__global__ void dconv_k(const float* __restrict__ w, const float* __restrict__ b) {
    int idx = blockIdx.x * blockDim.x + threadIdx.x;
    if (idx >= CM * CDI) return;
    int d = idx % CDI;
    int row = idx / CDI;
    int l = row % CL;
    const float* xp = g_xz + (long)row * (2 * CDI) + d;
    float4 wv = *(const float4*)(w + d * 4);
    float acc = b[d];
    if (l >= 3) acc = fmaf(xp[-3 * 2 * CDI], wv.x, acc);
    if (l >= 2) acc = fmaf(xp[-2 * 2 * CDI], wv.y, acc);
    if (l >= 1) acc = fmaf(xp[-1 * 2 * CDI], wv.z, acc);
    acc = fmaf(xp[0], wv.w, acc);
    float xv = siluf(acc);
    g_xc[idx] = xv;
    g_xch[idx] = __float2half_rn(xv);
}

__global__ __launch_bounds__(256) void scan_k(const float* __restrict__ Dskip) {
    int b = blockIdx.x >> 2;
    int d = ((blockIdx.x & 3) << 8) + threadIdx.x;
    float A[CDS], h[CDS];
    #pragma unroll
    for (int n = 0; n < CDS; n++) { A[n] = g_A[d * CDS + n]; h[n] = 0.f; }
    float Dv = Dskip[d];
    long base = (long)b * CL;
    for (int l = 0; l < CL; l++) {
        long r = base + l;
        float dtv = g_dt[r * CDI + d];
        float xv  = g_xc[r * CDI + d];
        const float4* bc = (const float4*)(g_dbc + r * 64 + 32);
        float4 B0 = bc[0], B1 = bc[1], B2 = bc[2], B3 = bc[3];
        float4 C0 = bc[4], C1 = bc[5], C2 = bc[6], C3 = bc[7];
        float Bv[CDS] = {B0.x,B0.y,B0.z,B0.w, B1.x,B1.y,B1.z,B1.w,
                         B2.x,B2.y,B2.z,B2.w, B3.x,B3.y,B3.z,B3.w};
        float Cv[CDS] = {C0.x,C0.y,C0.z,C0.w, C1.x,C1.y,C1.z,C1.w,
                         C2.x,C2.y,C2.z,C2.w, C3.x,C3.y,C3.z,C3.w};
        float dx = dtv * xv;
        float acc = 0.f;
        #pragma unroll
        for (int n = 0; n < CDS; n++) {
            float e = fexp(dtv * A[n]);
            h[n] = fmaf(e, h[n], dx * Bv[n]);
            acc = fmaf(h[n], Cv[n], acc);
        }
        float y = fmaf(xv, Dv, acc);
        float z = g_xz[r * (2 * CDI) + CDI + d];
        float o = y * siluf(z);
        g_ysh[r * CDI + d] = __float2half_rn(o);
    }
}

__global__ void final1_k(const float* __restrict__ lnw, const float* __restrict__ lnb,
                         const float* __restrict__ aw, const float* __restrict__ ab)
{
    int row = blockIdx.x;
    int t = threadIdx.x;
    __shared__ float sv[CDIM];
    float s = 0.f, s2 = 0.f;
    #pragma unroll
    for (int i = 0; i < 4; i++) {
        int c = t + i * 128;
        float v = g_m[(long)row * CDIM + c] + g_fts0[(long)row * CDIM + c];
        sv[c] = v;
        s += v; s2 += v * v;
    }
    blockRed2(s, s2);
    float mu = s * (1.f / CDIM);
    float var = s2 * (1.f / CDIM) - mu * mu;
    float rstd = rsqrtf(var + 1e-5f);
    float dot = 0.f;
    #pragma unroll
    for (int i = 0; i < 4; i++) {
        int c = t + i * 128;
        float x = (sv[c] - mu) * rstd * lnw[c] + lnb[c];
        dot += x * aw[c];
    }
    dot = blockRed1(dot);
    if (t == 0) g_coff[row] = dot + ab[0];
}

__global__ void final2_k(const float* __restrict__ bw, const float* __restrict__ bb,
                         float* __restrict__ out)
{
    int b = blockIdx.x;
    int t = threadIdx.x;
    float p = g_coff[b * CL + t] * bw[t];
    p = blockRed1(p);
    if (t == 0) out[b] = 1.f / (1.f + __expf(-(p + bb[0])));
}

extern "C" void kernel_launch(void* const* d_in, const int* in_sizes, int n_in,
                              void* d_out, int out_size)
{
    const float* spt       = (const float*)d_in[0];
    const float* qry       = (const float*)d_in[1];
    const float* conv_w    = (const float*)d_in[2];
    const float* conv_b    = (const float*)d_in[3];
    const float* ln_w      = (const float*)d_in[4];
    const float* ln_b      = (const float*)d_in[5];
    const float* in_proj_w = (const float*)d_in[6];
    const float* conv1d_w  = (const float*)d_in[7];
    const float* conv1d_b  = (const float*)d_in[8];
    const float* x_proj_w  = (const float*)d_in[9];
    const float* dt_proj_w = (const float*)d_in[10];
    const float* dt_proj_b = (const float*)d_in[11];
    const float* A_log     = (const float*)d_in[12];
    const float* D_skip    = (const float*)d_in[13];
    const float* out_proj_w= (const float*)d_in[14];
    const float* mlp_a_w   = (const float*)d_in[15];
    const float* mlp_a_b   = (const float*)d_in[16];
    const float* mlp_b_w   = (const float*)d_in[17];
    const float* mlp_b_b   = (const float*)d_in[18];
    float* out = (float*)d_out;

    float *p_conv, *p_dbc, *p_dt, *p_m, *p_xz;
    cudaGetSymbolAddress((void**)&p_conv, g_conv);
    cudaGetSymbolAddress((void**)&p_dbc,  g_dbc);
    cudaGetSymbolAddress((void**)&p_dt,   g_dt);
    cudaGetSymbolAddress((void**)&p_m,    g_m);
    cudaGetSymbolAddress((void**)&p_xz,   g_xz);
    __half *ph_pad, *ph_wt, *ph_f0, *ph_ipw, *ph_xc, *ph_xpw, *ph_ys, *ph_opw;
    cudaGetSymbolAddress((void**)&ph_pad, g_padh);
    cudaGetSymbolAddress((void**)&ph_wt,  g_wth);
    cudaGetSymbolAddress((void**)&ph_f0,  g_f0h);
    cudaGetSymbolAddress((void**)&ph_ipw, g_ipwh);
    cudaGetSymbolAddress((void**)&ph_xc,  g_xch);
    cudaGetSymbolAddress((void**)&ph_xpw, g_xpwh);
    cudaGetSymbolAddress((void**)&ph_ys,  g_ysh);
    cudaGetSymbolAddress((void**)&ph_opw, g_opwh);

    const int SM128 = 2 * ((128 + 128) * 80);  // 40960 B
    const int SM64  = 2 * ((128 + 64) * 80);   // 30720 B
    cudaFuncSetAttribute(tmma<128,1>, cudaFuncAttributeMaxDynamicSharedMemorySize, SM128);
    cudaFuncSetAttribute(tmma<128,0>, cudaFuncAttributeMaxDynamicSharedMemorySize, SM128);
    cudaFuncSetAttribute(tmma<64,0>,  cudaFuncAttributeMaxDynamicSharedMemorySize, SM64);

    pad_k<<<(CB*130*CDIM + 255)/256, 256>>>(spt, qry);
    wt_k<<<(CDIM*1536 + 255)/256, 256>>>(conv_w);
    a_k<<<(CDI*CDS + 255)/256, 256>>>(A_log);
    wcvt_k<<<(2*CDI*CDIM + 255)/256, 256>>>(in_proj_w, ph_ipw, 2*CDI*CDIM);
    wcvt_k<<<(64*CDI + 255)/256, 256>>>(x_proj_w, ph_xpw, 64*CDI);
    wcvt_k<<<(CDIM*CDI + 255)/256, 256>>>(out_proj_w, ph_opw, CDIM*CDI);

    // conv (SAME, k=3) as GEMM: M=8192 N=512 K=1536
    tmma<128,1><<<dim3(4,64), 256, SM128>>>(
        ph_pad, ph_wt, conv_b, p_conv,
        1536, 128, 130L*CDIM, (long)CDIM, 1536, CDIM);
    ln_relu_k<<<CM, 128>>>(p_conv, ln_w, ln_b);
    // in_proj: M=8192 N=2048 K=512
    tmma<128,0><<<dim3(16,64), 256, SM128>>>(
        ph_f0, ph_ipw, nullptr, p_xz,
        512, 1<<30, 0L, 512L, 512, 2048);
    dconv_k<<<(CM*CDI + 255)/256, 256>>>(conv1d_w, conv1d_b);
    // x_proj: M=8192 N=64 K=1024
    tmma<64,0><<<dim3(1,64), 256, SM64>>>(
        ph_xc, ph_xpw, nullptr, p_dbc,
        1024, 1<<30, 0L, 1024L, 1024, 64);
    // dt: M=8192 N=1024 K=32 (+bias, softplus)
    sgemm_nt<128,128,16,8,8,2><<<dim3(8,64), 256>>>(
        p_dbc, dt_proj_w, dt_proj_b, p_dt, 32, 1<<30, 0L, 64L, 32, CDI);
    scan_k<<<CB*4, 256>>>(D_skip);
    // out_proj: M=8192 N=512 K=1024
    tmma<128,0><<<dim3(4,64), 256, SM128>>>(
        ph_ys, ph_opw, nullptr, p_m,
        1024, 1<<30, 0L, 1024L, 1024, CDIM);
    final1_k<<<CM, 128>>>(ln_w, ln_b, mlp_a_w, mlp_a_b);
    final2_k<<<CB, 128>>>(mlp_b_w, mlp_b_b, out);
}

// round 13
// speedup vs baseline: 3.3102x; 1.2839x over previous
#include <cuda_runtime.h>
#include <cuda_fp16.h>
#include <math.h>
#include <stdint.h>

#define CDIM 512
#define CB   64
#define CL   128
#define CDI  1024
#define CDS  16
#define CM   (CB*CL)

// fp32 intermediates
__device__ __align__(16) float g_conv[CM*CDIM];
__device__ __align__(16) float g_fts0[CM*CDIM];
__device__ __align__(16) float g_dbc[CM*64];
__device__ __align__(16) float g_dt[CM*CDI];
__device__ __align__(16) float g_m[CM*CDIM];
__device__ __align__(16) float g_A[CDI*CDS];
__device__ __align__(16) float g_coff[CM];
// fp16 operands / activations
__device__ __align__(16) __half g_padh[CB*130*CDIM];
__device__ __align__(16) __half g_wth[CDIM*3*CDIM];
__device__ __align__(16) __half g_f0h[CM*CDIM];
__device__ __align__(16) __half g_ipwh[2*CDI*CDIM];
__device__ __align__(16) __half g_xch[CM*CDI];   // silu(depthwise conv(x))
__device__ __align__(16) __half g_szh[CM*CDI];   // silu(z)
__device__ __align__(16) __half g_xpwh[64*CDI];
__device__ __align__(16) __half g_ysh[CM*CDI];
__device__ __align__(16) __half g_opwh[CDIM*CDI];

__device__ __forceinline__ float softplusf(float x) {
    if (x > 20.f) return x;
    return log1pf(__expf(x));
}
__device__ __forceinline__ float siluf(float x) {
    return x / (1.f + __expf(-x));
}

__device__ __forceinline__ void blockRed2(float& a, float& b) {
    #pragma unroll
    for (int o = 16; o; o >>= 1) {
        a += __shfl_xor_sync(0xffffffffu, a, o);
        b += __shfl_xor_sync(0xffffffffu, b, o);
    }
    __shared__ float sa[4], sb[4];
    int w = threadIdx.x >> 5;
    if ((threadIdx.x & 31) == 0) { sa[w] = a; sb[w] = b; }
    __syncthreads();
    a = sa[0] + sa[1] + sa[2] + sa[3];
    b = sb[0] + sb[1] + sb[2] + sb[3];
    __syncthreads();
}
__device__ __forceinline__ float blockRed1(float a) {
    #pragma unroll
    for (int o = 16; o; o >>= 1) a += __shfl_xor_sync(0xffffffffu, a, o);
    __shared__ float sc[4];
    int w = threadIdx.x >> 5;
    if ((threadIdx.x & 31) == 0) sc[w] = a;
    __syncthreads();
    float t = sc[0] + sc[1] + sc[2] + sc[3];
    __syncthreads();
    return t;
}

__device__ __forceinline__ uint32_t smem_u32(const void* p) {
    uint32_t a;
    asm("{ .reg .u64 t; cvta.to.shared.u64 t, %1; cvt.u32.u64 %0, t; }" : "=r"(a) : "l"(p));
    return a;
}

#define LDSM4(rr, ad) \
    asm volatile("ldmatrix.sync.aligned.m8n8.x4.shared.b16 {%0,%1,%2,%3}, [%4];" \
        : "=r"((rr)[0]), "=r"((rr)[1]), "=r"((rr)[2]), "=r"((rr)[3]) : "r"(ad))

#define MMA_F16(cc, aa, bb) \
    asm volatile("mma.sync.aligned.m16n8k16.row.col.f32.f16.f16.f32 " \
        "{%0,%1,%2,%3}, {%4,%5,%6,%7}, {%8,%9}, {%0,%1,%2,%3};" \
        : "+f"((cc)[0]), "+f"((cc)[1]), "+f"((cc)[2]), "+f"((cc)[3]) \
        : "r"((aa)[0]), "r"((aa)[1]), "r"((aa)[2]), "r"((aa)[3]), \
          "r"((bb)[0]), "r"((bb)[1]))

// fp16 tensor GEMM via mma.sync. Block 128 x BN, BK=32, 2-stage cp.async.
// 8 warps: 2(m) x 4(n); warp tile 64 x (BN/4).
// C[m][n] = sum_k A[m][k]*W[n][k]; A_row(m) = A + (m/rb)*rbs + (m%rb)*rs
// EPI: 0 none, 1 +bias, 2 mamba in_proj (fused depthwise conv+silu on x half,
//      silu on z half; M-tile == one batch sequence so conv is tile-local)
template<int BN, int EPI>
__global__ __launch_bounds__(256)
void tmma(const __half* __restrict__ Ah, const __half* __restrict__ Wh,
          const float* __restrict__ bias, float* __restrict__ C,
          int K, int rb, long rbs, long rs, int ldw, int ldc,
          const float* __restrict__ cw, const float* __restrict__ cb,
          __half* __restrict__ xh, __half* __restrict__ zh)
{
    constexpr int ASTR  = 80;             // 64B data + 16B pad per smem row
    constexpr int ATILE = 128 * ASTR;
    constexpr int BTILE = BN * ASTR;
    constexpr int STAGE = ATILE + BTILE;
    constexpr int NCA = 128 * 4, NCB = BN * 4;   // 16B chunks
    constexpr int TOT = NCA + NCB;
    constexpr int WN = BN / 4;
    constexpr int NF = WN / 8;
    extern __shared__ __align__(128) char smem[];

    int tid = threadIdx.x, lane = tid & 31, wid = tid >> 5;
    int wm = wid & 1, wn = wid >> 1;
    int m0 = blockIdx.y * 128, n0 = blockIdx.x * BN;
    uint32_t sbase = smem_u32(smem);

    float c[4][NF][4];
    #pragma unroll
    for (int i = 0; i < 4; i++)
        #pragma unroll
        for (int j = 0; j < NF; j++)
            #pragma unroll
            for (int q = 0; q < 4; q++) c[i][j][q] = 0.f;

    auto loadStage = [&](int s) {
        int p = s & 1, k0 = s * 32;
        uint32_t sb = sbase + p * STAGE;
        #pragma unroll
        for (int it = 0; it < TOT / 256; it++) {
            int ch = tid + it * 256;
            const __half* g;
            uint32_t so;
            if (ch < NCA) {
                int row = ch >> 2, qo = ch & 3;
                int gm = m0 + row;
                g = Ah + (long)(gm / rb) * rbs + (long)(gm % rb) * rs + k0 + qo * 8;
                so = row * ASTR + qo * 16;
            } else {
                int cc = ch - NCA;
                int row = cc >> 2, qo = cc & 3;
                g = Wh + (long)(n0 + row) * ldw + k0 + qo * 8;
                so = ATILE + row * ASTR + qo * 16;
            }
            asm volatile("cp.async.cg.shared.global [%0], [%1], 16;"
                         :: "r"(sb + so), "l"((const void*)g));
        }
        asm volatile("cp.async.commit_group;" ::: "memory");
    };

    auto compStage = [&](int p) {
        uint32_t sb = sbase + p * STAGE;
        int mat = lane >> 3, r8 = lane & 7;
        #pragma unroll
        for (int kf = 0; kf < 2; kf++) {
            uint32_t ah[4][4], bh[NF][2];
            #pragma unroll
            for (int mf = 0; mf < 4; mf++) {
                uint32_t ad = sb + (uint32_t)((wm * 64 + mf * 16 + ((mat & 1) << 3) + r8) * ASTR
                                              + kf * 32 + ((mat >> 1) << 4));
                LDSM4(ah[mf], ad);
            }
            #pragma unroll
            for (int pp = 0; pp < NF / 2; pp++) {
                uint32_t bd = sb + ATILE
                            + (uint32_t)((wn * WN + pp * 16 + ((mat >> 1) << 3) + r8) * ASTR
                                         + kf * 32 + ((mat & 1) << 4));
                uint32_t t[4];
                LDSM4(t, bd);
                bh[2*pp][0] = t[0]; bh[2*pp][1] = t[1];
                bh[2*pp+1][0] = t[2]; bh[2*pp+1][1] = t[3];
            }
            #pragma unroll
            for (int mf = 0; mf < 4; mf++)
                #pragma unroll
                for (int nf = 0; nf < NF; nf++)
                    MMA_F16(c[mf][nf], ah[mf], bh[nf]);
        }
    };

    int S = K >> 5;
    loadStage(0);
    for (int s = 0; s < S; s++) {
        if (s + 1 < S) {
            loadStage(s + 1);
            asm volatile("cp.async.wait_group 1;" ::: "memory");
        } else {
            asm volatile("cp.async.wait_group 0;" ::: "memory");
        }
        __syncthreads();
        compStage(s & 1);
        __syncthreads();
    }

    if (EPI == 2) {
        // in_proj fused epilogue. M-tile = batch blockIdx.y, rows l=0..127.
        if (n0 < CDI) {
            // x half: stage fp32 tile, causal depthwise conv (K=4) + silu -> xh
            float* sx = (float*)smem;   // [128][132]
            #pragma unroll
            for (int mf = 0; mf < 4; mf++) {
                int r1 = wm * 64 + mf * 16 + (lane >> 2);
                #pragma unroll
                for (int nf = 0; nf < NF; nf++) {
                    int cc0 = wn * WN + nf * 8 + (lane & 3) * 2;
                    sx[r1 * 132 + cc0]       = c[mf][nf][0];
                    sx[r1 * 132 + cc0 + 1]   = c[mf][nf][1];
                    sx[(r1+8) * 132 + cc0]     = c[mf][nf][2];
                    sx[(r1+8) * 132 + cc0 + 1] = c[mf][nf][3];
                }
            }
            __syncthreads();
            int ccol = tid & 127, hf = tid >> 7;
            int gd = n0 + ccol;
            float4 wv = *(const float4*)(cw + gd * 4);
            float bb = cb[gd];
            int l0 = hf * 64;
            float xm3 = (l0 >= 3) ? sx[(l0-3) * 132 + ccol] : 0.f;
            float xm2 = (l0 >= 2) ? sx[(l0-2) * 132 + ccol] : 0.f;
            float xm1 = (l0 >= 1) ? sx[(l0-1) * 132 + ccol] : 0.f;
            #pragma unroll 8
            for (int l = l0; l < l0 + 64; l++) {
                float x0 = sx[l * 132 + ccol];
                float acc = bb;
                acc = fmaf(wv.x, xm3, acc);
                acc = fmaf(wv.y, xm2, acc);
                acc = fmaf(wv.z, xm1, acc);
                acc = fmaf(wv.w, x0,  acc);
                xh[(long)(m0 + l) * CDI + gd] = __float2half_rn(siluf(acc));
                xm3 = xm2; xm2 = xm1; xm1 = x0;
            }
        } else {
            // z half: silu -> zh
            #pragma unroll
            for (int mf = 0; mf < 4; mf++) {
                int gm0 = m0 + wm * 64 + mf * 16 + (lane >> 2);
                #pragma unroll
                for (int nf = 0; nf < NF; nf++) {
                    int gnl = (n0 - CDI) + wn * WN + nf * 8 + (lane & 3) * 2;
                    __half2 h0 = __floats2half2_rn(siluf(c[mf][nf][0]), siluf(c[mf][nf][1]));
                    __half2 h1 = __floats2half2_rn(siluf(c[mf][nf][2]), siluf(c[mf][nf][3]));
                    *(__half2*)(zh + (long)gm0 * CDI + gnl) = h0;
                    *(__half2*)(zh + (long)(gm0 + 8) * CDI + gnl) = h1;
                }
            }
        }
        return;
    }

    #pragma unroll
    for (int mf = 0; mf < 4; mf++) {
        int gm0 = m0 + wm * 64 + mf * 16 + (lane >> 2);
        #pragma unroll
        for (int nf = 0; nf < NF; nf++) {
            int gn = n0 + wn * WN + nf * 8 + (lane & 3) * 2;
            float2 v0 = make_float2(c[mf][nf][0], c[mf][nf][1]);
            float2 v1 = make_float2(c[mf][nf][2], c[mf][nf][3]);
            if (EPI == 1) {
                float b0 = bias[gn], b1 = bias[gn + 1];
                v0.x += b0; v0.y += b1; v1.x += b0; v1.y += b1;
            }
            *(float2*)(C + (long)gm0 * ldc + gn) = v0;
            *(float2*)(C + (long)(gm0 + 8) * ldc + gn) = v1;
        }
    }
}

// fp32 GEMM (tiny dt projection, K=32)
template<int BM, int BN, int BK, int TM, int TN, int EPI>
__global__ __launch_bounds__((BM/TM)*(BN/TN))
void sgemm_nt(const float* __restrict__ A, const float* __restrict__ W,
              const float* __restrict__ bias, float* __restrict__ C,
              int K, int rb, long rbs, long rs, int ldw, int ldc)
{
    constexpr int TX = BN / TN, TY = BM / TM, NT = TX * TY;
    constexpr int K4 = BK / 4;
    constexpr int ROWS_PER = NT / K4;
    static_assert(NT == 256, "thread count");

    __shared__ __align__(16) float As[BK][BM];
    __shared__ __align__(16) float Ws[BK][BN];

    int tid = threadIdx.x;
    int m0 = blockIdx.y * BM, n0 = blockIdx.x * BN;
    int tx = tid % TX, ty = tid / TX;
    int arow = tid / K4, ac4 = (tid % K4) * 4;

    float acc[TM][TN];
    #pragma unroll
    for (int i = 0; i < TM; i++)
        #pragma unroll
        for (int j = 0; j < TN; j++) acc[i][j] = 0.f;

    for (int k0 = 0; k0 < K; k0 += BK) {
        #pragma unroll
        for (int r = arow; r < BM; r += ROWS_PER) {
            int grow = m0 + r;
            const float* ap = A + (long)(grow / rb) * rbs + (long)(grow % rb) * rs + k0 + ac4;
            float4 v = *(const float4*)ap;
            As[ac4 + 0][r] = v.x; As[ac4 + 1][r] = v.y;
            As[ac4 + 2][r] = v.z; As[ac4 + 3][r] = v.w;
        }
        #pragma unroll
        for (int r = arow; r < BN; r += ROWS_PER) {
            const float* wp = W + (long)(n0 + r) * ldw + k0 + ac4;
            float4 v = *(const float4*)wp;
            Ws[ac4 + 0][r] = v.x; Ws[ac4 + 1][r] = v.y;
            Ws[ac4 + 2][r] = v.z; Ws[ac4 + 3][r] = v.w;
        }
        __syncthreads();
        #pragma unroll
        for (int k = 0; k < BK; k++) {
            float a[TM], wv[TN];
            #pragma unroll
            for (int i = 0; i < TM; i += 4) {
                float4 t = *(const float4*)&As[k][ty * TM + i];
                a[i] = t.x; a[i+1] = t.y; a[i+2] = t.z; a[i+3] = t.w;
            }
            #pragma unroll
            for (int j = 0; j < TN; j += 4) {
                float4 t = *(const float4*)&Ws[k][tx * TN + j];
                wv[j] = t.x; wv[j+1] = t.y; wv[j+2] = t.z; wv[j+3] = t.w;
            }
            #pragma unroll
            for (int i = 0; i < TM; i++)
                #pragma unroll
                for (int j = 0; j < TN; j++)
                    acc[i][j] = fmaf(a[i], wv[j], acc[i][j]);
        }
        __syncthreads();
    }

    #pragma unroll
    for (int i = 0; i < TM; i++) {
        int gm = m0 + ty * TM + i;
        float* cp = C + (long)gm * ldc + n0 + tx * TN;
        #pragma unroll
        for (int j = 0; j < TN; j += 4) {
            float4 v;
            float e0 = acc[i][j], e1 = acc[i][j+1], e2 = acc[i][j+2], e3 = acc[i][j+3];
            if (EPI >= 1) {
                int gn = n0 + tx * TN + j;
                e0 += bias[gn]; e1 += bias[gn+1]; e2 += bias[gn+2]; e3 += bias[gn+3];
            }
            if (EPI == 2) {
                e0 = softplusf(e0); e1 = softplusf(e1);
                e2 = softplusf(e2); e3 = softplusf(e3);
            }
            v.x = e0; v.y = e1; v.z = e2; v.w = e3;
            *(float4*)(cp + j) = v;
        }
    }
}

// ---------------------------------------------------------------------------
// Prep: conv-weight repack (launch 1)
// ---------------------------------------------------------------------------
__global__ void prep_w1(const float* __restrict__ cw) {
    int idx = blockIdx.x * blockDim.x + threadIdx.x;
    if (idx >= CDIM * 1536) return;
    int co = idx / 1536;
    int r  = idx % 1536;
    int k  = r / CDIM;
    int ci = r % CDIM;
    g_wth[idx] = __float2half_rn(cw[(co * CDIM + ci) * 3 + k]);
}
// Prep: other weight converts (launch 2): ipw | xpw | opw
__global__ void prep_w2(const float* __restrict__ ipw, const float* __restrict__ xpw,
                        const float* __restrict__ opw) {
    const int N1 = 2*CDI*CDIM, N2 = 64*CDI, N3 = CDIM*CDI;
    int idx = blockIdx.x * blockDim.x + threadIdx.x;
    if (idx < N1) { g_ipwh[idx] = __float2half_rn(ipw[idx]); return; }
    idx -= N1;
    if (idx < N2) { g_xpwh[idx] = __float2half_rn(xpw[idx]); return; }
    idx -= N2;
    if (idx < N3) { g_opwh[idx] = __float2half_rn(opw[idx]); }
}
// Prep: padded conv input + A (launch 3)
__global__ void prep_x(const float* __restrict__ spt, const float* __restrict__ qry,
                       const float* __restrict__ alog) {
    const int NP = CB * 130 * CDIM;
    int idx = blockIdx.x * blockDim.x + threadIdx.x;
    if (idx < NP) {
        int b = idx / (130 * CDIM);
        int r = idx % (130 * CDIM);
        int l = r / CDIM;
        int c = r % CDIM;
        float v = 0.f;
        if (l >= 1 && l <= 128) {
            int ll = l - 1;
            v = (ll < 64) ? spt[b * 32768 + ll * CDIM + c]
                          : qry[b * 32768 + (ll - 64) * CDIM + c];
        }
        g_padh[idx] = __float2half_rn(v);
        return;
    }
    idx -= NP;
    if (idx < CDI * CDS) g_A[idx] = -expf(alog[idx]);
}

__global__ void ln_relu_k(const float* __restrict__ in, const float* __restrict__ w,
                          const float* __restrict__ b)
{
    int row = blockIdx.x;
    int t = threadIdx.x;
    const float* p = in + (long)row * CDIM;
    float v[4], s = 0.f, s2 = 0.f;
    #pragma unroll
    for (int i = 0; i < 4; i++) {
        v[i] = p[t + i * 128];
        s += v[i]; s2 += v[i] * v[i];
    }
    blockRed2(s, s2);
    float mu = s * (1.f / CDIM);
    float var = s2 * (1.f / CDIM) - mu * mu;
    float rstd = rsqrtf(var + 1e-5f);
    #pragma unroll
    for (int i = 0; i < 4; i++) {
        int c = t + i * 128;
        long o = (long)row * CDIM + c;
        float x = (v[i] - mu) * rstd * w[c] + b[c];
        x = fmaxf(x, 0.f);
        g_fts0[o] = x;
        g_f0h[o] = __float2half_rn(x);
    }
}

// Selective scan: one thread per (b,d), __expf (MUFU) for the state decay
__global__ __launch_bounds__(256) void scan_k(const float* __restrict__ Dskip) {
    int b = blockIdx.x >> 2;
    int d = ((blockIdx.x & 3) << 8) + threadIdx.x;
    float A[CDS], h[CDS];
    #pragma unroll
    for (int n = 0; n < CDS; n++) { A[n] = g_A[d * CDS + n]; h[n] = 0.f; }
    float Dv = Dskip[d];
    long base = (long)b * CL;
    for (int l = 0; l < CL; l++) {
        long r = base + l;
        float dtv = g_dt[r * CDI + d];
        float xv  = __half2float(g_xch[r * CDI + d]);
        const float4* bc = (const float4*)(g_dbc + r * 64 + 32);
        float4 B0 = bc[0], B1 = bc[1], B2 = bc[2], B3 = bc[3];
        float4 C0 = bc[4], C1 = bc[5], C2 = bc[6], C3 = bc[7];
        float Bv[CDS] = {B0.x,B0.y,B0.z,B0.w, B1.x,B1.y,B1.z,B1.w,
                         B2.x,B2.y,B2.z,B2.w, B3.x,B3.y,B3.z,B3.w};
        float Cv[CDS] = {C0.x,C0.y,C0.z,C0.w, C1.x,C1.y,C1.z,C1.w,
                         C2.x,C2.y,C2.z,C2.w, C3.x,C3.y,C3.z,C3.w};
        float dx = dtv * xv;
        float acc = 0.f;
        #pragma unroll
        for (int n = 0; n < CDS; n++) {
            float e = __expf(dtv * A[n]);
            h[n] = fmaf(e, h[n], dx * Bv[n]);
            acc = fmaf(h[n], Cv[n], acc);
        }
        float y = fmaf(xv, Dv, acc);
        float sz = __half2float(g_szh[r * CDI + d]);
        g_ysh[r * CDI + d] = __float2half_rn(y * sz);
    }
}

__global__ void final1_k(const float* __restrict__ lnw, const float* __restrict__ lnb,
                         const float* __restrict__ aw, const float* __restrict__ ab)
{
    int row = blockIdx.x;
    int t = threadIdx.x;
    __shared__ float sv[CDIM];
    float s = 0.f, s2 = 0.f;
    #pragma unroll
    for (int i = 0; i < 4; i++) {
        int c = t + i * 128;
        float v = g_m[(long)row * CDIM + c] + g_fts0[(long)row * CDIM + c];
        sv[c] = v;
        s += v; s2 += v * v;
    }
    blockRed2(s, s2);
    float mu = s * (1.f / CDIM);
    float var = s2 * (1.f / CDIM) - mu * mu;
    float rstd = rsqrtf(var + 1e-5f);
    float dot = 0.f;
    #pragma unroll
    for (int i = 0; i < 4; i++) {
        int c = t + i * 128;
        float x = (sv[c] - mu) * rstd * lnw[c] + lnb[c];
        dot += x * aw[c];
    }
    dot = blockRed1(dot);
    if (t == 0) g_coff[row] = dot + ab[0];
}

__global__ void final2_k(const float* __restrict__ bw, const float* __restrict__ bb,
                         float* __restrict__ out)
{
    int b = blockIdx.x;
    int t = threadIdx.x;
    float p = g_coff[b * CL + t] * bw[t];
    p = blockRed1(p);
    if (t == 0) out[b] = 1.f / (1.f + __expf(-(p + bb[0])));
}

extern "C" void kernel_launch(void* const* d_in, const int* in_sizes, int n_in,
                              void* d_out, int out_size)
{
    const float* spt       = (const float*)d_in[0];
    const float* qry       = (const float*)d_in[1];
    const float* conv_w    = (const float*)d_in[2];
    const float* conv_b    = (const float*)d_in[3];
    const float* ln_w      = (const float*)d_in[4];
    const float* ln_b      = (const float*)d_in[5];
    const float* in_proj_w = (const float*)d_in[6];
    const float* conv1d_w  = (const float*)d_in[7];
    const float* conv1d_b  = (const float*)d_in[8];
    const float* x_proj_w  = (const float*)d_in[9];
    const float* dt_proj_w = (const float*)d_in[10];
    const float* dt_proj_b = (const float*)d_in[11];
    const float* A_log     = (const float*)d_in[12];
    const float* D_skip    = (const float*)d_in[13];
    const float* out_proj_w= (const float*)d_in[14];
    const float* mlp_a_w   = (const float*)d_in[15];
    const float* mlp_a_b   = (const float*)d_in[16];
    const float* mlp_b_w   = (const float*)d_in[17];
    const float* mlp_b_b   = (const float*)d_in[18];
    float* out = (float*)d_out;

    float *p_conv, *p_dbc, *p_dt, *p_m;
    cudaGetSymbolAddress((void**)&p_conv, g_conv);
    cudaGetSymbolAddress((void**)&p_dbc,  g_dbc);
    cudaGetSymbolAddress((void**)&p_dt,   g_dt);
    cudaGetSymbolAddress((void**)&p_m,    g_m);
    __half *ph_pad, *ph_wt, *ph_f0, *ph_ipw, *ph_xc, *ph_sz, *ph_xpw, *ph_ys, *ph_opw;
    cudaGetSymbolAddress((void**)&ph_pad, g_padh);
    cudaGetSymbolAddress((void**)&ph_wt,  g_wth);
    cudaGetSymbolAddress((void**)&ph_f0,  g_f0h);
    cudaGetSymbolAddress((void**)&ph_ipw, g_ipwh);
    cudaGetSymbolAddress((void**)&ph_xc,  g_xch);
    cudaGetSymbolAddress((void**)&ph_sz,  g_szh);
    cudaGetSymbolAddress((void**)&ph_xpw, g_xpwh);
    cudaGetSymbolAddress((void**)&ph_ys,  g_ysh);
    cudaGetSymbolAddress((void**)&ph_opw, g_opwh);

    const int SM128 = 2 * ((128 + 128) * 80);      // 40960 B (plain tmma)
    const int SMIP  = 128 * 132 * 4;               // 67584 B (fused in_proj)
    const int SM64  = 2 * ((128 + 64) * 80);       // 30720 B
    cudaFuncSetAttribute(tmma<128,1>, cudaFuncAttributeMaxDynamicSharedMemorySize, SM128);
    cudaFuncSetAttribute(tmma<128,0>, cudaFuncAttributeMaxDynamicSharedMemorySize, SM128);
    cudaFuncSetAttribute(tmma<128,2>, cudaFuncAttributeMaxDynamicSharedMemorySize, SMIP);
    cudaFuncSetAttribute(tmma<64,0>,  cudaFuncAttributeMaxDynamicSharedMemorySize, SM64);

    // 1: conv-weight repack
    prep_w1<<<(CDIM*1536 + 255)/256, 256>>>(conv_w);
    // 2: remaining weight converts
    prep_w2<<<(2*CDI*CDIM + 64*CDI + CDIM*CDI + 255)/256, 256>>>(in_proj_w, x_proj_w, out_proj_w);
    // 3: padded conv input + A
    prep_x<<<(CB*130*CDIM + CDI*CDS + 255)/256, 256>>>(spt, qry, A_log);

    // 4: conv (SAME, k=3) as GEMM: M=8192 N=512 K=1536
    tmma<128,1><<<dim3(4,64), 256, SM128>>>(
        ph_pad, ph_wt, conv_b, p_conv,
        1536, 128, 130L*CDIM, (long)CDIM, 1536, CDIM,
        nullptr, nullptr, nullptr, nullptr);
    // 5: LN + ReLU
    ln_relu_k<<<CM, 128>>>(p_conv, ln_w, ln_b);
    // 6 (profiled): in_proj M=8192 N=2048 K=512, fused dconv+silu / silu(z)
    tmma<128,2><<<dim3(16,64), 256, SMIP>>>(
        ph_f0, ph_ipw, nullptr, nullptr,
        512, 1<<30, 0L, 512L, 512, 0,
        conv1d_w, conv1d_b, ph_xc, ph_sz);
    // 7: x_proj M=8192 N=64 K=1024
    tmma<64,0><<<dim3(1,64), 256, SM64>>>(
        ph_xc, ph_xpw, nullptr, p_dbc,
        1024, 1<<30, 0L, 1024L, 1024, 64,
        nullptr, nullptr, nullptr, nullptr);
    // 8: dt M=8192 N=1024 K=32 (+bias, softplus)
    sgemm_nt<128,128,16,8,8,2><<<dim3(8,64), 256>>>(
        p_dbc, dt_proj_w, dt_proj_b, p_dt, 32, 1<<30, 0L, 64L, 32, CDI);
    // 9: selective scan
    scan_k<<<CB*4, 256>>>(D_skip);
    // 10: out_proj M=8192 N=512 K=1024
    tmma<128,0><<<dim3(4,64), 256, SM128>>>(
        ph_ys, ph_opw, nullptr, p_m,
        1024, 1<<30, 0L, 1024L, 1024, CDIM,
        nullptr, nullptr, nullptr, nullptr);
    // 11: residual + LN + mlp_a dot
    final1_k<<<CM, 128>>>(ln_w, ln_b, mlp_a_w, mlp_a_b);
    // 12: mlp_b + sigmoid
    final2_k<<<CB, 128>>>(mlp_b_w, mlp_b_b, out);
}